// round 1
// baseline (speedup 1.0000x reference)
#include <cuda_runtime.h>
#include <math.h>

#define NN      10000
#define NE      160000
#define ET      170000     // NE + NN self loops
#define IN_DIM  256
#define HID     128
#define HEADS   8
#define F1      1024       // HEADS*HID
#define ODIM    64

// ---------------- scratch (device globals; no allocation) ----------------
__device__ float g_xl1  [NN * F1];      // x @ W1
__device__ float g_h1   [NN * F1];      // layer-1 aggregation -> elu(h)
__device__ float g_asrc1[NN * HEADS];
__device__ float g_adst1[NN * HEADS];
__device__ float g_emax1[NN * HEADS];
__device__ float g_den1 [NN * HEADS];
__device__ float g_ebuf [ET * HEADS];   // per-edge attention scratch (layer2 reuses first ET)
__device__ float g_h2   [NN * ODIM];    // h @ W2
__device__ float g_h2agg[NN * ODIM];
__device__ float g_asrc2[NN];
__device__ float g_adst2[NN];
__device__ float g_emax2[NN];
__device__ float g_den2 [NN];

// ---------------- helpers ----------------
__device__ __forceinline__ void edge_sd(const int* __restrict__ ei, int e, int& s, int& d) {
    if (e < NE) { s = ei[e]; d = ei[NE + e]; }
    else        { s = e - NE; d = e - NE; }
}

__device__ __forceinline__ void atomicMaxF(float* addr, float val) {
    int* ia = (int*)addr;
    int old = *ia;
    while (__int_as_float(old) < val) {
        int assumed = old;
        old = atomicCAS(ia, assumed, __float_as_int(val));
        if (old == assumed) break;
    }
}

// ---------------- init ----------------
__global__ void k_init() {
    int i = blockIdx.x * blockDim.x + threadIdx.x;
    if (i < NN * F1)   g_h1[i] = 0.f;
    if (i < NN * ODIM) g_h2agg[i] = 0.f;
    if (i < NN * HEADS) { g_den1[i] = 0.f; g_emax1[i] = -1e30f; }
    if (i < NN)         { g_den2[i] = 0.f; g_emax2[i] = -1e30f; }
}

// ---------------- generic tiled SGEMM: C[M,N] = A[M,K] @ B[K,N] ----------------
template<int BM, int BN, int BK, int TM, int TN>
__global__ void k_sgemm(const float* __restrict__ A, const float* __restrict__ B,
                        float* __restrict__ C, int M, int N, int K) {
    constexpr int NT = (BM / TM) * (BN / TN);
    __shared__ float As[BK][BM];
    __shared__ float Bs[BK][BN];
    int tid = threadIdx.x;
    int tx = tid % (BN / TN);
    int ty = tid / (BN / TN);
    int row0 = blockIdx.y * BM;
    int col0 = blockIdx.x * BN;

    float acc[TM][TN];
    #pragma unroll
    for (int i = 0; i < TM; i++)
        #pragma unroll
        for (int j = 0; j < TN; j++) acc[i][j] = 0.f;

    for (int k0 = 0; k0 < K; k0 += BK) {
        #pragma unroll 4
        for (int i = tid; i < BM * BK; i += NT) {
            int r = i / BK, c = i % BK;
            int gr = row0 + r;
            As[c][r] = (gr < M) ? A[gr * K + k0 + c] : 0.f;
        }
        #pragma unroll 4
        for (int i = tid; i < BK * BN; i += NT) {
            int r = i / BN, c = i % BN;
            int gc = col0 + c;
            Bs[r][c] = (gc < N) ? B[(k0 + r) * N + gc] : 0.f;
        }
        __syncthreads();
        #pragma unroll
        for (int kk = 0; kk < BK; kk++) {
            float a[TM], b[TN];
            #pragma unroll
            for (int i = 0; i < TM; i++) a[i] = As[kk][ty * TM + i];
            #pragma unroll
            for (int j = 0; j < TN; j++) b[j] = Bs[kk][tx * TN + j];
            #pragma unroll
            for (int i = 0; i < TM; i++)
                #pragma unroll
                for (int j = 0; j < TN; j++) acc[i][j] += a[i] * b[j];
        }
        __syncthreads();
    }
    #pragma unroll
    for (int i = 0; i < TM; i++) {
        int gr = row0 + ty * TM + i;
        if (gr >= M) continue;
        #pragma unroll
        for (int j = 0; j < TN; j++) {
            int gc = col0 + tx * TN + j;
            if (gc < N) C[gr * N + gc] = acc[i][j];
        }
    }
}

// ---------------- layer-1 attention coefficients (warp per node*head) ----------------
__global__ void k_attn1(const float* __restrict__ att_src, const float* __restrict__ att_dst) {
    int w = (blockIdx.x * blockDim.x + threadIdx.x) >> 5;
    int lane = threadIdx.x & 31;
    if (w >= NN * HEADS) return;
    int n = w >> 3, h = w & 7;
    const float* v = g_xl1 + n * F1 + h * HID;
    float s1 = 0.f, s2 = 0.f;
    #pragma unroll
    for (int c = lane; c < HID; c += 32) {
        float x = v[c];
        s1 += x * att_src[h * HID + c];
        s2 += x * att_dst[h * HID + c];
    }
    #pragma unroll
    for (int o = 16; o; o >>= 1) {
        s1 += __shfl_xor_sync(~0u, s1, o);
        s2 += __shfl_xor_sync(~0u, s2, o);
    }
    if (!lane) { g_asrc1[w] = s1; g_adst1[w] = s2; }
}

// ---------------- layer-1 edge pass A: leaky + segment max ----------------
__global__ void k_edge_max1(const int* __restrict__ ei) {
    int i = blockIdx.x * blockDim.x + threadIdx.x;
    if (i >= ET * HEADS) return;
    int e = i >> 3, h = i & 7;
    int s, d; edge_sd(ei, e, s, d);
    float v = g_asrc1[s * HEADS + h] + g_adst1[d * HEADS + h];
    v = v > 0.f ? v : 0.2f * v;
    g_ebuf[i] = v;
    atomicMaxF(&g_emax1[d * HEADS + h], v);
}

// ---------------- layer-1 edge pass B: exp + segment sum ----------------
__global__ void k_edge_exp1(const int* __restrict__ ei) {
    int i = blockIdx.x * blockDim.x + threadIdx.x;
    if (i >= ET * HEADS) return;
    int e = i >> 3, h = i & 7;
    int s, d; edge_sd(ei, e, s, d);
    float w = expf(g_ebuf[i] - g_emax1[d * HEADS + h]);
    g_ebuf[i] = w;
    atomicAdd(&g_den1[d * HEADS + h], w);
}

// ---------------- layer-1 aggregation: block per edge, 1024 channels ----------------
__global__ void k_agg1(const int* __restrict__ ei) {
    int e = blockIdx.x;
    int s, d; edge_sd(ei, e, s, d);
    int t = threadIdx.x;
    const float* xs = g_xl1 + s * F1;
    float*       od = g_h1  + d * F1;
    #pragma unroll
    for (int i = 0; i < 4; i++) {
        int c = t + i * 256;
        int h = c >> 7;
        float alpha = g_ebuf[e * HEADS + h] / (g_den1[d * HEADS + h] + 1e-16f);
        atomicAdd(&od[c], alpha * xs[c]);
    }
}

// ---------------- bias + ELU (in place on g_h1) ----------------
__global__ void k_bias_elu(const float* __restrict__ b1) {
    int i = blockIdx.x * blockDim.x + threadIdx.x;
    if (i >= NN * F1) return;
    float v = g_h1[i] + b1[i & (F1 - 1)];
    g_h1[i] = v > 0.f ? v : expm1f(v);
}

// ---------------- layer-2 attention coefficients (warp per node) ----------------
__global__ void k_attn2(const float* __restrict__ att_src, const float* __restrict__ att_dst) {
    int w = (blockIdx.x * blockDim.x + threadIdx.x) >> 5;
    int lane = threadIdx.x & 31;
    if (w >= NN) return;
    const float* v = g_h2 + w * ODIM;
    float s1 = v[lane] * att_src[lane] + v[lane + 32] * att_src[lane + 32];
    float s2 = v[lane] * att_dst[lane] + v[lane + 32] * att_dst[lane + 32];
    #pragma unroll
    for (int o = 16; o; o >>= 1) {
        s1 += __shfl_xor_sync(~0u, s1, o);
        s2 += __shfl_xor_sync(~0u, s2, o);
    }
    if (!lane) { g_asrc2[w] = s1; g_adst2[w] = s2; }
}

__global__ void k_edge_max2(const int* __restrict__ ei) {
    int e = blockIdx.x * blockDim.x + threadIdx.x;
    if (e >= ET) return;
    int s, d; edge_sd(ei, e, s, d);
    float v = g_asrc2[s] + g_adst2[d];
    v = v > 0.f ? v : 0.2f * v;
    g_ebuf[e] = v;
    atomicMaxF(&g_emax2[d], v);
}

__global__ void k_edge_exp2(const int* __restrict__ ei) {
    int e = blockIdx.x * blockDim.x + threadIdx.x;
    if (e >= ET) return;
    int s, d; edge_sd(ei, e, s, d);
    float w = expf(g_ebuf[e] - g_emax2[d]);
    g_ebuf[e] = w;
    atomicAdd(&g_den2[d], w);
}

// ---------------- layer-2 aggregation: thread per (edge, channel) ----------------
__global__ void k_agg2(const int* __restrict__ ei) {
    int i = blockIdx.x * blockDim.x + threadIdx.x;
    if (i >= ET * ODIM) return;
    int e = i >> 6, c = i & 63;
    int s, d; edge_sd(ei, e, s, d);
    float alpha = g_ebuf[e] / (g_den2[d] + 1e-16f);
    atomicAdd(&g_h2agg[d * ODIM + c], alpha * g_h2[s * ODIM + c]);
}

// ---------------- bias + LayerNorm + affine (warp per node) ----------------
__global__ void k_ln(const float* __restrict__ b2, const float* __restrict__ gamma,
                     const float* __restrict__ beta, float* __restrict__ out) {
    int w = (blockIdx.x * blockDim.x + threadIdx.x) >> 5;
    int lane = threadIdx.x & 31;
    if (w >= NN) return;
    float v0 = g_h2agg[w * ODIM + lane]      + b2[lane];
    float v1 = g_h2agg[w * ODIM + lane + 32] + b2[lane + 32];
    float s = v0 + v1;
    #pragma unroll
    for (int o = 16; o; o >>= 1) s += __shfl_xor_sync(~0u, s, o);
    float mu = s * (1.f / 64.f);
    float d0 = v0 - mu, d1 = v1 - mu;
    float q = d0 * d0 + d1 * d1;
    #pragma unroll
    for (int o = 16; o; o >>= 1) q += __shfl_xor_sync(~0u, q, o);
    float inv = rsqrtf(q * (1.f / 64.f) + 1e-5f);
    out[w * ODIM + lane]      = d0 * inv * gamma[lane]      + beta[lane];
    out[w * ODIM + lane + 32] = d1 * inv * gamma[lane + 32] + beta[lane + 32];
}

// ---------------- launch ----------------
extern "C" void kernel_launch(void* const* d_in, const int* in_sizes, int n_in,
                              void* d_out, int out_size) {
    const float* x     = (const float*)d_in[0];
    const int*   ei    = (const int*)  d_in[1];
    const float* W1    = (const float*)d_in[2];
    const float* as1   = (const float*)d_in[3];
    const float* ad1   = (const float*)d_in[4];
    const float* b1    = (const float*)d_in[5];
    const float* W2    = (const float*)d_in[6];
    const float* as2   = (const float*)d_in[7];
    const float* ad2   = (const float*)d_in[8];
    const float* b2    = (const float*)d_in[9];
    const float* gamma = (const float*)d_in[10];
    const float* beta  = (const float*)d_in[11];
    float* out = (float*)d_out;

    float *xl1, *h1, *h2;
    cudaGetSymbolAddress((void**)&xl1, g_xl1);
    cudaGetSymbolAddress((void**)&h1,  g_h1);
    cudaGetSymbolAddress((void**)&h2,  g_h2);

    k_init<<<(NN * F1 + 255) / 256, 256>>>();

    {   // GEMM1: [10000,256] @ [256,1024]
        dim3 g((F1 + 127) / 128, (NN + 127) / 128);
        k_sgemm<128, 128, 8, 8, 8><<<g, 256>>>(x, W1, xl1, NN, F1, IN_DIM);
    }
    k_attn1<<<(NN * HEADS * 32 + 255) / 256, 256>>>(as1, ad1);
    k_edge_max1<<<(ET * HEADS + 255) / 256, 256>>>(ei);
    k_edge_exp1<<<(ET * HEADS + 255) / 256, 256>>>(ei);
    k_agg1<<<ET, 256>>>(ei);
    k_bias_elu<<<(NN * F1 + 255) / 256, 256>>>(b1);

    {   // GEMM2: [10000,1024] @ [1024,64]
        dim3 g((ODIM + 63) / 64, (NN + 63) / 64);
        k_sgemm<64, 64, 16, 4, 4><<<g, 256>>>(h1, W2, h2, NN, ODIM, F1);
    }
    k_attn2<<<(NN * 32 + 255) / 256, 256>>>(as2, ad2);
    k_edge_max2<<<(ET + 255) / 256, 256>>>(ei);
    k_edge_exp2<<<(ET + 255) / 256, 256>>>(ei);
    k_agg2<<<(ET * ODIM + 255) / 256, 256>>>(ei);
    k_ln<<<(NN * 32 + 255) / 256, 256>>>(b2, gamma, beta, out);
}

// round 2
// speedup vs baseline: 1.5369x; 1.5369x over previous
#include <cuda_runtime.h>
#include <math.h>

#define NN      10000
#define NE      160000
#define ET      170000     // NE + NN self loops
#define IN_DIM  256
#define HID     128
#define HEADS   8
#define F1      1024       // HEADS*HID
#define ODIM    64

// ---------------- scratch (device globals; no allocation) ----------------
__device__ float g_xl1  [NN * F1];      // x @ W1
__device__ float g_h1   [NN * F1];      // layer-1 output (bias+elu fused)
__device__ float g_asrc1[NN * HEADS];
__device__ float g_adst1[NN * HEADS];
__device__ float g_alpha1[ET * HEADS];  // per CSR-slot, per head
__device__ float g_h2   [NN * ODIM];    // h @ W2
__device__ float g_h2agg[NN * ODIM];
__device__ float g_asrc2[NN];
__device__ float g_adst2[NN];
__device__ float g_alpha2[ET];          // per CSR-slot

// CSR by destination
__device__ int g_deg   [NN];
__device__ int g_cursor[NN];
__device__ int g_rowptr[NN + 1];
__device__ int g_csrsrc[ET];            // src node per CSR slot

// ---------------- helpers ----------------
__device__ __forceinline__ void edge_sd(const int* __restrict__ ei, int e, int& s, int& d) {
    if (e < NE) { s = ei[e]; d = ei[NE + e]; }
    else        { s = e - NE; d = e - NE; }
}

// ---------------- CSR build ----------------
__global__ void k_csr_init() {
    int i = blockIdx.x * blockDim.x + threadIdx.x;
    if (i < NN) { g_deg[i] = 0; g_cursor[i] = 0; }
}

__global__ void k_deg(const int* __restrict__ ei) {
    int e = blockIdx.x * blockDim.x + threadIdx.x;
    if (e >= ET) return;
    int d = (e < NE) ? ei[NE + e] : (e - NE);
    atomicAdd(&g_deg[d], 1);
}

// single-block exclusive prefix sum over NN degrees (warp-shuffle scan)
__global__ void k_scan() {
    __shared__ int warpsum[32];
    __shared__ int carry_s;
    int t = threadIdx.x, lane = t & 31, w = t >> 5;
    if (t == 0) carry_s = 0;
    __syncthreads();
    for (int base = 0; base < NN; base += 1024) {
        int i = base + t;
        int x = (i < NN) ? g_deg[i] : 0;
        #pragma unroll
        for (int o = 1; o < 32; o <<= 1) {
            int y = __shfl_up_sync(~0u, x, o);
            if (lane >= o) x += y;
        }
        if (lane == 31) warpsum[w] = x;
        __syncthreads();
        if (w == 0) {
            int s = warpsum[lane];
            #pragma unroll
            for (int o = 1; o < 32; o <<= 1) {
                int y = __shfl_up_sync(~0u, s, o);
                if (lane >= o) s += y;
            }
            warpsum[lane] = s;
        }
        __syncthreads();
        int incl = x + (w ? warpsum[w - 1] : 0) + carry_s;
        if (i < NN) g_rowptr[i + 1] = incl;
        __syncthreads();
        if (t == 1023) carry_s = incl;
        __syncthreads();
    }
    if (threadIdx.x == 0) g_rowptr[0] = 0;
}

__global__ void k_scatter(const int* __restrict__ ei) {
    int e = blockIdx.x * blockDim.x + threadIdx.x;
    if (e >= ET) return;
    int s, d; edge_sd(ei, e, s, d);
    int pos = atomicAdd(&g_cursor[d], 1);
    g_csrsrc[g_rowptr[d] + pos] = s;
}

// ---------------- generic tiled SGEMM: C[M,N] = A[M,K] @ B[K,N] ----------------
template<int BM, int BN, int BK, int TM, int TN>
__global__ void k_sgemm(const float* __restrict__ A, const float* __restrict__ B,
                        float* __restrict__ C, int M, int N, int K) {
    constexpr int NT = (BM / TM) * (BN / TN);
    __shared__ float As[BK][BM];
    __shared__ float Bs[BK][BN];
    int tid = threadIdx.x;
    int tx = tid % (BN / TN);
    int ty = tid / (BN / TN);
    int row0 = blockIdx.y * BM;
    int col0 = blockIdx.x * BN;

    float acc[TM][TN];
    #pragma unroll
    for (int i = 0; i < TM; i++)
        #pragma unroll
        for (int j = 0; j < TN; j++) acc[i][j] = 0.f;

    for (int k0 = 0; k0 < K; k0 += BK) {
        #pragma unroll 4
        for (int i = tid; i < BM * BK; i += NT) {
            int r = i / BK, c = i % BK;
            int gr = row0 + r;
            As[c][r] = (gr < M) ? A[gr * K + k0 + c] : 0.f;
        }
        #pragma unroll 4
        for (int i = tid; i < BK * BN; i += NT) {
            int r = i / BN, c = i % BN;
            int gc = col0 + c;
            Bs[r][c] = (gc < N) ? B[(k0 + r) * N + gc] : 0.f;
        }
        __syncthreads();
        #pragma unroll
        for (int kk = 0; kk < BK; kk++) {
            float a[TM], b[TN];
            #pragma unroll
            for (int i = 0; i < TM; i++) a[i] = As[kk][ty * TM + i];
            #pragma unroll
            for (int j = 0; j < TN; j++) b[j] = Bs[kk][tx * TN + j];
            #pragma unroll
            for (int i = 0; i < TM; i++)
                #pragma unroll
                for (int j = 0; j < TN; j++) acc[i][j] += a[i] * b[j];
        }
        __syncthreads();
    }
    #pragma unroll
    for (int i = 0; i < TM; i++) {
        int gr = row0 + ty * TM + i;
        if (gr >= M) continue;
        #pragma unroll
        for (int j = 0; j < TN; j++) {
            int gc = col0 + tx * TN + j;
            if (gc < N) C[gr * N + gc] = acc[i][j];
        }
    }
}

// ---------------- layer-1 attention coefficients (warp per node*head) ----------------
__global__ void k_attn1(const float* __restrict__ att_src, const float* __restrict__ att_dst) {
    int w = (blockIdx.x * blockDim.x + threadIdx.x) >> 5;
    int lane = threadIdx.x & 31;
    if (w >= NN * HEADS) return;
    int n = w >> 3, h = w & 7;
    const float* v = g_xl1 + n * F1 + h * HID;
    float s1 = 0.f, s2 = 0.f;
    #pragma unroll
    for (int c = lane; c < HID; c += 32) {
        float x = v[c];
        s1 += x * att_src[h * HID + c];
        s2 += x * att_dst[h * HID + c];
    }
    #pragma unroll
    for (int o = 16; o; o >>= 1) {
        s1 += __shfl_xor_sync(~0u, s1, o);
        s2 += __shfl_xor_sync(~0u, s2, o);
    }
    if (!lane) { g_asrc1[w] = s1; g_adst1[w] = s2; }
}

// ---------------- layer-1 segment softmax (thread per dst*head, CSR walk) ----------------
__global__ void k_softmax1() {
    int t = blockIdx.x * blockDim.x + threadIdx.x;
    if (t >= NN * HEADS) return;
    int d = t >> 3, h = t & 7;
    int jb = g_rowptr[d], je = g_rowptr[d + 1];
    float adst = g_adst1[t];
    float m = -1e30f;
    for (int j = jb; j < je; j++) {
        int s = g_csrsrc[j];
        float v = g_asrc1[s * HEADS + h] + adst;
        v = v > 0.f ? v : 0.2f * v;
        g_alpha1[j * HEADS + h] = v;
        m = fmaxf(m, v);
    }
    float den = 0.f;
    for (int j = jb; j < je; j++)
        den += expf(g_alpha1[j * HEADS + h] - m);
    float r = 1.f / (den + 1e-16f);
    for (int j = jb; j < je; j++)
        g_alpha1[j * HEADS + h] = expf(g_alpha1[j * HEADS + h] - m) * r;
}

// ---------------- layer-1 aggregation: block per dst, no atomics, fused bias+ELU ---------
__global__ void k_agg1(const float* __restrict__ b1) {
    int d = blockIdx.x;
    int t = threadIdx.x;              // float4 index: channels [4t, 4t+3]
    int h = t >> 5;                   // head of this channel group
    int jb = g_rowptr[d], je = g_rowptr[d + 1];
    const float4* xl = (const float4*)g_xl1;
    float4 acc = make_float4(0.f, 0.f, 0.f, 0.f);
    for (int j = jb; j < je; j++) {
        int s = g_csrsrc[j];
        float a = g_alpha1[j * HEADS + h];
        float4 xv = xl[s * (F1 / 4) + t];
        acc.x += a * xv.x; acc.y += a * xv.y;
        acc.z += a * xv.z; acc.w += a * xv.w;
    }
    float4 bb = ((const float4*)b1)[t];
    acc.x += bb.x; acc.y += bb.y; acc.z += bb.z; acc.w += bb.w;
    acc.x = acc.x > 0.f ? acc.x : expm1f(acc.x);
    acc.y = acc.y > 0.f ? acc.y : expm1f(acc.y);
    acc.z = acc.z > 0.f ? acc.z : expm1f(acc.z);
    acc.w = acc.w > 0.f ? acc.w : expm1f(acc.w);
    ((float4*)g_h1)[d * (F1 / 4) + t] = acc;
}

// ---------------- layer-2 attention coefficients (warp per node) ----------------
__global__ void k_attn2(const float* __restrict__ att_src, const float* __restrict__ att_dst) {
    int w = (blockIdx.x * blockDim.x + threadIdx.x) >> 5;
    int lane = threadIdx.x & 31;
    if (w >= NN) return;
    const float* v = g_h2 + w * ODIM;
    float s1 = v[lane] * att_src[lane] + v[lane + 32] * att_src[lane + 32];
    float s2 = v[lane] * att_dst[lane] + v[lane + 32] * att_dst[lane + 32];
    #pragma unroll
    for (int o = 16; o; o >>= 1) {
        s1 += __shfl_xor_sync(~0u, s1, o);
        s2 += __shfl_xor_sync(~0u, s2, o);
    }
    if (!lane) { g_asrc2[w] = s1; g_adst2[w] = s2; }
}

// ---------------- layer-2 segment softmax (thread per dst) ----------------
__global__ void k_softmax2() {
    int d = blockIdx.x * blockDim.x + threadIdx.x;
    if (d >= NN) return;
    int jb = g_rowptr[d], je = g_rowptr[d + 1];
    float adst = g_adst2[d];
    float m = -1e30f;
    for (int j = jb; j < je; j++) {
        float v = g_asrc2[g_csrsrc[j]] + adst;
        v = v > 0.f ? v : 0.2f * v;
        g_alpha2[j] = v;
        m = fmaxf(m, v);
    }
    float den = 0.f;
    for (int j = jb; j < je; j++) den += expf(g_alpha2[j] - m);
    float r = 1.f / (den + 1e-16f);
    for (int j = jb; j < je; j++) g_alpha2[j] = expf(g_alpha2[j] - m) * r;
}

// ---------------- layer-2 aggregation: 4 dsts per block, no atomics ----------------
__global__ void k_agg2() {
    int d = blockIdx.x * 4 + (threadIdx.x >> 6);
    int c = threadIdx.x & 63;
    if (d >= NN) return;
    int jb = g_rowptr[d], je = g_rowptr[d + 1];
    float acc = 0.f;
    for (int j = jb; j < je; j++) {
        int s = g_csrsrc[j];
        acc += g_alpha2[j] * g_h2[s * ODIM + c];
    }
    g_h2agg[d * ODIM + c] = acc;
}

// ---------------- bias + LayerNorm + affine (warp per node) ----------------
__global__ void k_ln(const float* __restrict__ b2, const float* __restrict__ gamma,
                     const float* __restrict__ beta, float* __restrict__ out) {
    int w = (blockIdx.x * blockDim.x + threadIdx.x) >> 5;
    int lane = threadIdx.x & 31;
    if (w >= NN) return;
    float v0 = g_h2agg[w * ODIM + lane]      + b2[lane];
    float v1 = g_h2agg[w * ODIM + lane + 32] + b2[lane + 32];
    float s = v0 + v1;
    #pragma unroll
    for (int o = 16; o; o >>= 1) s += __shfl_xor_sync(~0u, s, o);
    float mu = s * (1.f / 64.f);
    float d0 = v0 - mu, d1 = v1 - mu;
    float q = d0 * d0 + d1 * d1;
    #pragma unroll
    for (int o = 16; o; o >>= 1) q += __shfl_xor_sync(~0u, q, o);
    float inv = rsqrtf(q * (1.f / 64.f) + 1e-5f);
    out[w * ODIM + lane]      = d0 * inv * gamma[lane]      + beta[lane];
    out[w * ODIM + lane + 32] = d1 * inv * gamma[lane + 32] + beta[lane + 32];
}

// ---------------- launch ----------------
extern "C" void kernel_launch(void* const* d_in, const int* in_sizes, int n_in,
                              void* d_out, int out_size) {
    const float* x     = (const float*)d_in[0];
    const int*   ei    = (const int*)  d_in[1];
    const float* W1    = (const float*)d_in[2];
    const float* as1   = (const float*)d_in[3];
    const float* ad1   = (const float*)d_in[4];
    const float* b1    = (const float*)d_in[5];
    const float* W2    = (const float*)d_in[6];
    const float* as2   = (const float*)d_in[7];
    const float* ad2   = (const float*)d_in[8];
    const float* b2    = (const float*)d_in[9];
    const float* gamma = (const float*)d_in[10];
    const float* beta  = (const float*)d_in[11];
    float* out = (float*)d_out;

    float *xl1, *h1, *h2;
    cudaGetSymbolAddress((void**)&xl1, g_xl1);
    cudaGetSymbolAddress((void**)&h1,  g_h1);
    cudaGetSymbolAddress((void**)&h2,  g_h2);

    // CSR build (can overlap conceptually with GEMM1; stream is serial anyway)
    k_csr_init<<<(NN + 255) / 256, 256>>>();
    k_deg<<<(ET + 255) / 256, 256>>>(ei);
    k_scan<<<1, 1024>>>();
    k_scatter<<<(ET + 255) / 256, 256>>>(ei);

    {   // GEMM1: [10000,256] @ [256,1024]
        dim3 g((F1 + 127) / 128, (NN + 127) / 128);
        k_sgemm<128, 128, 8, 8, 8><<<g, 256>>>(x, W1, xl1, NN, F1, IN_DIM);
    }
    k_attn1<<<(NN * HEADS * 32 + 255) / 256, 256>>>(as1, ad1);
    k_softmax1<<<(NN * HEADS + 255) / 256, 256>>>();
    k_agg1<<<NN, 256>>>(b1);

    {   // GEMM2: [10000,1024] @ [1024,64]
        dim3 g((ODIM + 63) / 64, (NN + 63) / 64);
        k_sgemm<64, 64, 16, 4, 4><<<g, 256>>>(h1, W2, h2, NN, ODIM, F1);
    }
    k_attn2<<<(NN * 32 + 255) / 256, 256>>>(as2, ad2);
    k_softmax2<<<(NN + 255) / 256, 256>>>();
    k_agg2<<<(NN + 3) / 4, 256>>>();
    k_ln<<<(NN * 32 + 255) / 256, 256>>>(b2, gamma, beta, out);
}

// round 5
// speedup vs baseline: 2.4446x; 1.5906x over previous
#include <cuda_runtime.h>
#include <cuda_bf16.h>
#include <math.h>
#include <stdint.h>

#define NN      10000
#define NE      160000
#define ET      170000
#define IN_DIM  256
#define HID     128
#define HEADS   8
#define F1      1024
#define ODIM    64

#define K1E     (3 * IN_DIM)   // 768  : GEMM1 extended K
#define K2E     (3 * F1)       // 3072 : GEMM2 extended K

// ================= scratch (device globals; no allocation) =================
__device__ float g_xl1  [NN * F1];
__device__ float g_asrc1[NN * HEADS];
__device__ float g_adst1[NN * HEADS];
__device__ float g_alpha1[ET * HEADS];
__device__ float g_h2   [NN * ODIM];
__device__ float g_h2agg[NN * ODIM];
__device__ float g_asrc2[NN];
__device__ float g_adst2[NN];
__device__ float g_alpha2[ET];
__device__ int g_deg   [NN];
__device__ int g_cursor[NN];
__device__ int g_rowptr[NN + 1];
__device__ int g_csrsrc[ET];
// bf16 hi/lo-extended operands (K-folded 3-term split)
__device__ __nv_bfloat16 g_xe  [NN * K1E];     // [10000][768]  = [hi | hi | lo]
__device__ __nv_bfloat16 g_w1e [F1 * K1E];     // [1024][768]   = [hi | lo | hi] (B-side)
__device__ __nv_bfloat16 g_h1e [NN * K2E];     // [10000][3072] = [hi | hi | lo]
__device__ __nv_bfloat16 g_w2e [ODIM * K2E];   // [64][3072]    = [hi | lo | hi]

// ================= CSR build =================
__device__ __forceinline__ void edge_sd(const int* __restrict__ ei, int e, int& s, int& d) {
    if (e < NE) { s = ei[e]; d = ei[NE + e]; }
    else        { s = e - NE; d = e - NE; }
}
__global__ void k_csr_init() {
    int i = blockIdx.x * blockDim.x + threadIdx.x;
    if (i < NN) { g_deg[i] = 0; g_cursor[i] = 0; }
}
__global__ void k_deg(const int* __restrict__ ei) {
    int e = blockIdx.x * blockDim.x + threadIdx.x;
    if (e >= ET) return;
    int d = (e < NE) ? ei[NE + e] : (e - NE);
    atomicAdd(&g_deg[d], 1);
}
__global__ void k_scan() {
    __shared__ int warpsum[32];
    __shared__ int carry_s;
    int t = threadIdx.x, lane = t & 31, w = t >> 5;
    if (t == 0) carry_s = 0;
    __syncthreads();
    for (int base = 0; base < NN; base += 1024) {
        int i = base + t;
        int x = (i < NN) ? g_deg[i] : 0;
        #pragma unroll
        for (int o = 1; o < 32; o <<= 1) {
            int y = __shfl_up_sync(~0u, x, o);
            if (lane >= o) x += y;
        }
        if (lane == 31) warpsum[w] = x;
        __syncthreads();
        if (w == 0) {
            int s = warpsum[lane];
            #pragma unroll
            for (int o = 1; o < 32; o <<= 1) {
                int y = __shfl_up_sync(~0u, s, o);
                if (lane >= o) s += y;
            }
            warpsum[lane] = s;
        }
        __syncthreads();
        int incl = x + (w ? warpsum[w - 1] : 0) + carry_s;
        if (i < NN) g_rowptr[i + 1] = incl;
        __syncthreads();
        if (t == 1023) carry_s = incl;
        __syncthreads();
    }
    if (threadIdx.x == 0) g_rowptr[0] = 0;
}
__global__ void k_scatter(const int* __restrict__ ei) {
    int e = blockIdx.x * blockDim.x + threadIdx.x;
    if (e >= ET) return;
    int s, d; edge_sd(ei, e, s, d);
    int pos = atomicAdd(&g_cursor[d], 1);
    g_csrsrc[g_rowptr[d] + pos] = s;
}

// ================= hi/lo-extended conversion =================
__global__ void k_cvt_x(const float* __restrict__ x) {
    int i = blockIdx.x * blockDim.x + threadIdx.x;
    if (i >= NN * IN_DIM) return;
    float v = x[i];
    __nv_bfloat16 hi = __float2bfloat16(v);
    __nv_bfloat16 lo = __float2bfloat16(v - __bfloat162float(hi));
    int r = i >> 8, k = i & (IN_DIM - 1);
    __nv_bfloat16* row = g_xe + (size_t)r * K1E;
    row[k] = hi; row[k + IN_DIM] = hi; row[k + 2 * IN_DIM] = lo;
}
__global__ void k_cvt_w1(const float* __restrict__ W1) {  // W1: [256][1024]
    int i = blockIdx.x * blockDim.x + threadIdx.x;
    if (i >= IN_DIM * F1) return;
    int k = i >> 10, n = i & (F1 - 1);
    float v = W1[i];
    __nv_bfloat16 hi = __float2bfloat16(v);
    __nv_bfloat16 lo = __float2bfloat16(v - __bfloat162float(hi));
    __nv_bfloat16* row = g_w1e + (size_t)n * K1E;
    row[k] = hi; row[k + IN_DIM] = lo; row[k + 2 * IN_DIM] = hi;
}
__global__ void k_cvt_w2(const float* __restrict__ W2) {  // W2: [1024][64]
    int i = blockIdx.x * blockDim.x + threadIdx.x;
    if (i >= F1 * ODIM) return;
    int k = i >> 6, n = i & (ODIM - 1);
    float v = W2[i];
    __nv_bfloat16 hi = __float2bfloat16(v);
    __nv_bfloat16 lo = __float2bfloat16(v - __bfloat162float(hi));
    __nv_bfloat16* row = g_w2e + (size_t)n * K2E;
    row[k] = hi; row[k + F1] = lo; row[k + 2 * F1] = hi;
}

// ================= bf16 mma.sync GEMM: C[M,N] = A[M,K] @ B[N,K]^T =================
__device__ __forceinline__ void mma16816(float* c, const uint32_t* a, const uint32_t* b) {
    asm volatile(
        "mma.sync.aligned.m16n8k16.row.col.f32.bf16.bf16.f32 "
        "{%0,%1,%2,%3}, {%4,%5,%6,%7}, {%8,%9}, {%0,%1,%2,%3};"
        : "+f"(c[0]), "+f"(c[1]), "+f"(c[2]), "+f"(c[3])
        : "r"(a[0]), "r"(a[1]), "r"(a[2]), "r"(a[3]), "r"(b[0]), "r"(b[1]));
}

template<int BM, int BN, int WM, int WN>
__global__ void __launch_bounds__(256) k_mma_gemm(
        const __nv_bfloat16* __restrict__ A,  // [M][K]
        const __nv_bfloat16* __restrict__ B,  // [N][K]
        float* __restrict__ C, int M, int N, int K) {
    constexpr int WT_M = BM / WM;
    constexpr int WT_N = BN / WN;
    constexpr int MF = WT_M / 16;
    constexpr int NF = WT_N / 8;
    constexpr int LDS = 40;                 // padded row stride (elems)
    constexpr int A_LD = BM * 4 / 256;      // uint4 loads per thread for A tile (BMx32)
    constexpr int B_LD = BN * 4 / 256;      // uint4 loads per thread for B tile (BNx32)

    __shared__ __nv_bfloat16 As[2][BM * LDS];
    __shared__ __nv_bfloat16 Bs[2][BN * LDS];

    int tid = threadIdx.x;
    int w = tid >> 5, lane = tid & 31;
    int g = lane >> 2, t4 = lane & 3;
    int wm = w / WN, wn = w % WN;
    int m0 = blockIdx.y * BM;
    int n0 = blockIdx.x * BN;
    int wrow = wm * WT_M, wcol = wn * WT_N;

    float acc[MF][NF][4];
    #pragma unroll
    for (int i = 0; i < MF; i++)
        #pragma unroll
        for (int j = 0; j < NF; j++)
            #pragma unroll
            for (int q = 0; q < 4; q++) acc[i][j][q] = 0.f;

    const uint4 zero4 = make_uint4(0, 0, 0, 0);
    int NIT = K / 32;
    uint4 pa[A_LD], pb[B_LD];

    auto load_g = [&](int k0) {
        #pragma unroll
        for (int q = 0; q < A_LD; q++) {
            int idx = tid + q * 256;
            int row = idx >> 2, seg = idx & 3;
            int gr = m0 + row;
            pa[q] = (gr < M) ? *(const uint4*)(A + (size_t)gr * K + k0 + seg * 8) : zero4;
        }
        #pragma unroll
        for (int q = 0; q < B_LD; q++) {
            int idx = tid + q * 256;
            if (B_LD * 256 == BN * 4 || idx < BN * 4) {
                int row = idx >> 2, seg = idx & 3;
                pb[q] = *(const uint4*)(B + (size_t)(n0 + row) * K + k0 + seg * 8);
            }
        }
    };
    auto store_s = [&](int buf) {
        #pragma unroll
        for (int q = 0; q < A_LD; q++) {
            int idx = tid + q * 256;
            int row = idx >> 2, seg = idx & 3;
            *(uint4*)&As[buf][row * LDS + seg * 8] = pa[q];
        }
        #pragma unroll
        for (int q = 0; q < B_LD; q++) {
            int idx = tid + q * 256;
            if (B_LD * 256 == BN * 4 || idx < BN * 4) {
                int row = idx >> 2, seg = idx & 3;
                *(uint4*)&Bs[buf][row * LDS + seg * 8] = pb[q];
            }
        }
    };

    load_g(0);
    store_s(0);
    __syncthreads();

    for (int it = 0; it < NIT; it++) {
        int buf = it & 1;
        if (it + 1 < NIT) load_g((it + 1) * 32);
        #pragma unroll
        for (int ks = 0; ks < 32; ks += 16) {
            uint32_t af[MF][4], bf[NF][2];
            #pragma unroll
            for (int mi = 0; mi < MF; mi++) {
                int r = wrow + mi * 16 + g;
                const __nv_bfloat16* base = &As[buf][0];
                af[mi][0] = *(const uint32_t*)&base[(r)     * LDS + ks + 2 * t4];
                af[mi][1] = *(const uint32_t*)&base[(r + 8) * LDS + ks + 2 * t4];
                af[mi][2] = *(const uint32_t*)&base[(r)     * LDS + ks + 2 * t4 + 8];
                af[mi][3] = *(const uint32_t*)&base[(r + 8) * LDS + ks + 2 * t4 + 8];
            }
            #pragma unroll
            for (int ni = 0; ni < NF; ni++) {
                int c = wcol + ni * 8 + g;
                const __nv_bfloat16* base = &Bs[buf][0];
                bf[ni][0] = *(const uint32_t*)&base[c * LDS + ks + 2 * t4];
                bf[ni][1] = *(const uint32_t*)&base[c * LDS + ks + 2 * t4 + 8];
            }
            #pragma unroll
            for (int mi = 0; mi < MF; mi++)
                #pragma unroll
                for (int ni = 0; ni < NF; ni++)
                    mma16816(acc[mi][ni], af[mi], bf[ni]);
        }
        __syncthreads();
        if (it + 1 < NIT) {
            store_s(buf ^ 1);
            __syncthreads();
        }
    }

    #pragma unroll
    for (int mi = 0; mi < MF; mi++) {
        #pragma unroll
        for (int ni = 0; ni < NF; ni++) {
            int r = m0 + wrow + mi * 16 + g;
            int c = n0 + wcol + ni * 8 + 2 * t4;
            if (r < M)     *(float2*)&C[(size_t)r * N + c]       = make_float2(acc[mi][ni][0], acc[mi][ni][1]);
            if (r + 8 < M) *(float2*)&C[(size_t)(r + 8) * N + c] = make_float2(acc[mi][ni][2], acc[mi][ni][3]);
        }
    }
}

// ================= GAT glue kernels =================
__global__ void k_attn1(const float* __restrict__ att_src, const float* __restrict__ att_dst) {
    int w = (blockIdx.x * blockDim.x + threadIdx.x) >> 5;
    int lane = threadIdx.x & 31;
    if (w >= NN * HEADS) return;
    int n = w >> 3, h = w & 7;
    const float* v = g_xl1 + n * F1 + h * HID;
    float s1 = 0.f, s2 = 0.f;
    #pragma unroll
    for (int c = lane; c < HID; c += 32) {
        float x = v[c];
        s1 += x * att_src[h * HID + c];
        s2 += x * att_dst[h * HID + c];
    }
    #pragma unroll
    for (int o = 16; o; o >>= 1) {
        s1 += __shfl_xor_sync(~0u, s1, o);
        s2 += __shfl_xor_sync(~0u, s2, o);
    }
    if (!lane) { g_asrc1[w] = s1; g_adst1[w] = s2; }
}
__global__ void k_softmax1() {
    int t = blockIdx.x * blockDim.x + threadIdx.x;
    if (t >= NN * HEADS) return;
    int d = t >> 3, h = t & 7;
    int jb = g_rowptr[d], je = g_rowptr[d + 1];
    float adst = g_adst1[t];
    float m = -1e30f;
    for (int j = jb; j < je; j++) {
        int s = g_csrsrc[j];
        float v = g_asrc1[s * HEADS + h] + adst;
        v = v > 0.f ? v : 0.2f * v;
        g_alpha1[j * HEADS + h] = v;
        m = fmaxf(m, v);
    }
    float den = 0.f;
    for (int j = jb; j < je; j++)
        den += expf(g_alpha1[j * HEADS + h] - m);
    float r = 1.f / (den + 1e-16f);
    for (int j = jb; j < je; j++)
        g_alpha1[j * HEADS + h] = expf(g_alpha1[j * HEADS + h] - m) * r;
}
// block per dst; fused bias+ELU; writes GEMM2 operand rows [hi | hi | lo] directly
__global__ void k_agg1(const float* __restrict__ b1) {
    int d = blockIdx.x;
    int t = threadIdx.x;
    int h = t >> 5;
    int jb = g_rowptr[d], je = g_rowptr[d + 1];
    const float4* xl = (const float4*)g_xl1;
    float4 acc = make_float4(0.f, 0.f, 0.f, 0.f);
    for (int j = jb; j < je; j++) {
        int s = g_csrsrc[j];
        float a = g_alpha1[j * HEADS + h];
        float4 xv = xl[s * (F1 / 4) + t];
        acc.x += a * xv.x; acc.y += a * xv.y;
        acc.z += a * xv.z; acc.w += a * xv.w;
    }
    float4 bb = ((const float4*)b1)[t];
    float v[4];
    v[0] = acc.x + bb.x; v[1] = acc.y + bb.y; v[2] = acc.z + bb.z; v[3] = acc.w + bb.w;
    #pragma unroll
    for (int q = 0; q < 4; q++) v[q] = v[q] > 0.f ? v[q] : expm1f(v[q]);
    __nv_bfloat16 hi[4], lo[4];
    #pragma unroll
    for (int q = 0; q < 4; q++) {
        hi[q] = __float2bfloat16(v[q]);
        lo[q] = __float2bfloat16(v[q] - __bfloat162float(hi[q]));
    }
    uint2 hp = *(uint2*)hi;
    uint2 lp = *(uint2*)lo;
    __nv_bfloat16* row = g_h1e + (size_t)d * K2E;
    *(uint2*)&row[4 * t]            = hp;
    *(uint2*)&row[4 * t + F1]       = hp;
    *(uint2*)&row[4 * t + 2 * F1]   = lp;
}
__global__ void k_attn2(const float* __restrict__ att_src, const float* __restrict__ att_dst) {
    int w = (blockIdx.x * blockDim.x + threadIdx.x) >> 5;
    int lane = threadIdx.x & 31;
    if (w >= NN) return;
    const float* v = g_h2 + w * ODIM;
    float s1 = v[lane] * att_src[lane] + v[lane + 32] * att_src[lane + 32];
    float s2 = v[lane] * att_dst[lane] + v[lane + 32] * att_dst[lane + 32];
    #pragma unroll
    for (int o = 16; o; o >>= 1) {
        s1 += __shfl_xor_sync(~0u, s1, o);
        s2 += __shfl_xor_sync(~0u, s2, o);
    }
    if (!lane) { g_asrc2[w] = s1; g_adst2[w] = s2; }
}
__global__ void k_softmax2() {
    int d = blockIdx.x * blockDim.x + threadIdx.x;
    if (d >= NN) return;
    int jb = g_rowptr[d], je = g_rowptr[d + 1];
    float adst = g_adst2[d];
    float m = -1e30f;
    for (int j = jb; j < je; j++) {
        float v = g_asrc2[g_csrsrc[j]] + adst;
        v = v > 0.f ? v : 0.2f * v;
        g_alpha2[j] = v;
        m = fmaxf(m, v);
    }
    float den = 0.f;
    for (int j = jb; j < je; j++) den += expf(g_alpha2[j] - m);
    float r = 1.f / (den + 1e-16f);
    for (int j = jb; j < je; j++) g_alpha2[j] = expf(g_alpha2[j] - m) * r;
}
__global__ void k_agg2() {
    int d = blockIdx.x * 4 + (threadIdx.x >> 6);
    int c = threadIdx.x & 63;
    if (d >= NN) return;
    int jb = g_rowptr[d], je = g_rowptr[d + 1];
    float acc = 0.f;
    for (int j = jb; j < je; j++) {
        int s = g_csrsrc[j];
        acc += g_alpha2[j] * g_h2[s * ODIM + c];
    }
    g_h2agg[d * ODIM + c] = acc;
}
__global__ void k_ln(const float* __restrict__ b2, const float* __restrict__ gamma,
                     const float* __restrict__ beta, float* __restrict__ out) {
    int w = (blockIdx.x * blockDim.x + threadIdx.x) >> 5;
    int lane = threadIdx.x & 31;
    if (w >= NN) return;
    float v0 = g_h2agg[w * ODIM + lane]      + b2[lane];
    float v1 = g_h2agg[w * ODIM + lane + 32] + b2[lane + 32];
    float s = v0 + v1;
    #pragma unroll
    for (int o = 16; o; o >>= 1) s += __shfl_xor_sync(~0u, s, o);
    float mu = s * (1.f / 64.f);
    float d0 = v0 - mu, d1 = v1 - mu;
    float q = d0 * d0 + d1 * d1;
    #pragma unroll
    for (int o = 16; o; o >>= 1) q += __shfl_xor_sync(~0u, q, o);
    float inv = rsqrtf(q * (1.f / 64.f) + 1e-5f);
    out[w * ODIM + lane]      = d0 * inv * gamma[lane]      + beta[lane];
    out[w * ODIM + lane + 32] = d1 * inv * gamma[lane + 32] + beta[lane + 32];
}

// ================= launch =================
extern "C" void kernel_launch(void* const* d_in, const int* in_sizes, int n_in,
                              void* d_out, int out_size) {
    const float* x     = (const float*)d_in[0];
    const int*   ei    = (const int*)  d_in[1];
    const float* W1    = (const float*)d_in[2];
    const float* as1   = (const float*)d_in[3];
    const float* ad1   = (const float*)d_in[4];
    const float* b1    = (const float*)d_in[5];
    const float* W2    = (const float*)d_in[6];
    const float* as2   = (const float*)d_in[7];
    const float* ad2   = (const float*)d_in[8];
    const float* b2    = (const float*)d_in[9];
    const float* gamma = (const float*)d_in[10];
    const float* beta  = (const float*)d_in[11];
    float* out = (float*)d_out;

    __nv_bfloat16 *xe, *w1e, *h1e, *w2e;
    float *xl1, *h2;
    cudaGetSymbolAddress((void**)&xe,  g_xe);
    cudaGetSymbolAddress((void**)&w1e, g_w1e);
    cudaGetSymbolAddress((void**)&h1e, g_h1e);
    cudaGetSymbolAddress((void**)&w2e, g_w2e);
    cudaGetSymbolAddress((void**)&xl1, g_xl1);
    cudaGetSymbolAddress((void**)&h2,  g_h2);

    // CSR build
    k_csr_init<<<(NN + 255) / 256, 256>>>();
    k_deg<<<(ET + 255) / 256, 256>>>(ei);
    k_scan<<<1, 1024>>>();
    k_scatter<<<(ET + 255) / 256, 256>>>(ei);

    // operand conversion + GEMM1 on tensor cores
    k_cvt_x<<<(NN * IN_DIM + 255) / 256, 256>>>(x);
    k_cvt_w1<<<(IN_DIM * F1 + 255) / 256, 256>>>(W1);
    k_cvt_w2<<<(F1 * ODIM + 255) / 256, 256>>>(W2);
    {
        dim3 g(F1 / 128, (NN + 127) / 128);
        k_mma_gemm<128, 128, 2, 4><<<g, 256>>>(xe, w1e, xl1, NN, F1, K1E);
    }

    k_attn1<<<(NN * HEADS * 32 + 255) / 256, 256>>>(as1, ad1);
    k_softmax1<<<(NN * HEADS + 255) / 256, 256>>>();
    k_agg1<<<NN, 256>>>(b1);

    {   // GEMM2: [10000,3072e] @ [3072e,64]
        dim3 g(ODIM / 64, (NN + 127) / 128);
        k_mma_gemm<128, 64, 4, 2><<<g, 256>>>(h1e, w2e, h2, NN, ODIM, K2E);
    }
    k_attn2<<<(NN * 32 + 255) / 256, 256>>>(as2, ad2);
    k_softmax2<<<(NN + 255) / 256, 256>>>();
    k_agg2<<<(NN + 3) / 4, 256>>>();
    k_ln<<<(NN * 32 + 255) / 256, 256>>>(b2, gamma, beta, out);
}

// round 6
// speedup vs baseline: 2.8278x; 1.1568x over previous
#include <cuda_runtime.h>
#include <cuda_bf16.h>
#include <math.h>
#include <stdint.h>

#define NN      10000
#define NE      160000
#define ET      170000
#define IN_DIM  256
#define HID     128
#define HEADS   8
#define F1      1024
#define ODIM    64

#define K1E     (3 * IN_DIM)   // 768
#define K2E     (3 * F1)       // 3072

// ================= scratch (device globals; no allocation) =================
__device__ float g_xl1  [NN * F1];
__device__ float g_asrc1[NN * HEADS];
__device__ float g_adst1[NN * HEADS];
__device__ float g_h2   [NN * ODIM];
__device__ float g_asrc2[NN];
__device__ float g_adst2[NN];
__device__ int g_deg   [NN];
__device__ int g_cursor[NN];
__device__ int g_rowptr[NN + 1];
__device__ int g_csrsrc[ET];
__device__ __nv_bfloat16 g_xe  [NN * K1E];     // [hi | hi | lo]
__device__ __nv_bfloat16 g_w1e [F1 * K1E];     // [hi | lo | hi]
__device__ __nv_bfloat16 g_h1e [NN * K2E];     // [hi | hi | lo]
__device__ __nv_bfloat16 g_w2e [ODIM * K2E];   // [hi | lo | hi]

// ================= CSR build =================
__device__ __forceinline__ void edge_sd(const int* __restrict__ ei, int e, int& s, int& d) {
    if (e < NE) { s = ei[e]; d = ei[NE + e]; }
    else        { s = e - NE; d = e - NE; }
}
__global__ void k_csr_init() {
    int i = blockIdx.x * blockDim.x + threadIdx.x;
    if (i < NN) { g_deg[i] = 0; g_cursor[i] = 0; }
}
__global__ void k_deg(const int* __restrict__ ei) {
    int e = blockIdx.x * blockDim.x + threadIdx.x;
    if (e >= ET) return;
    int d = (e < NE) ? ei[NE + e] : (e - NE);
    atomicAdd(&g_deg[d], 1);
}
__global__ void k_scan() {
    __shared__ int warpsum[32];
    __shared__ int carry_s;
    int t = threadIdx.x, lane = t & 31, w = t >> 5;
    if (t == 0) carry_s = 0;
    __syncthreads();
    for (int base = 0; base < NN; base += 1024) {
        int i = base + t;
        int x = (i < NN) ? g_deg[i] : 0;
        #pragma unroll
        for (int o = 1; o < 32; o <<= 1) {
            int y = __shfl_up_sync(~0u, x, o);
            if (lane >= o) x += y;
        }
        if (lane == 31) warpsum[w] = x;
        __syncthreads();
        if (w == 0) {
            int s = warpsum[lane];
            #pragma unroll
            for (int o = 1; o < 32; o <<= 1) {
                int y = __shfl_up_sync(~0u, s, o);
                if (lane >= o) s += y;
            }
            warpsum[lane] = s;
        }
        __syncthreads();
        int incl = x + (w ? warpsum[w - 1] : 0) + carry_s;
        if (i < NN) g_rowptr[i + 1] = incl;
        __syncthreads();
        if (t == 1023) carry_s = incl;
        __syncthreads();
    }
    if (threadIdx.x == 0) g_rowptr[0] = 0;
}
__global__ void k_scatter(const int* __restrict__ ei) {
    int e = blockIdx.x * blockDim.x + threadIdx.x;
    if (e >= ET) return;
    int s, d; edge_sd(ei, e, s, d);
    int pos = atomicAdd(&g_cursor[d], 1);
    g_csrsrc[g_rowptr[d] + pos] = s;
}

// ================= hi/lo-extended conversion =================
__global__ void k_cvt_x(const float* __restrict__ x) {
    int i = blockIdx.x * blockDim.x + threadIdx.x;
    if (i >= NN * IN_DIM) return;
    float v = x[i];
    __nv_bfloat16 hi = __float2bfloat16(v);
    __nv_bfloat16 lo = __float2bfloat16(v - __bfloat162float(hi));
    int r = i >> 8, k = i & (IN_DIM - 1);
    __nv_bfloat16* row = g_xe + (size_t)r * K1E;
    row[k] = hi; row[k + IN_DIM] = hi; row[k + 2 * IN_DIM] = lo;
}
__global__ void k_cvt_w1(const float* __restrict__ W1) {
    int i = blockIdx.x * blockDim.x + threadIdx.x;
    if (i >= IN_DIM * F1) return;
    int k = i >> 10, n = i & (F1 - 1);
    float v = W1[i];
    __nv_bfloat16 hi = __float2bfloat16(v);
    __nv_bfloat16 lo = __float2bfloat16(v - __bfloat162float(hi));
    __nv_bfloat16* row = g_w1e + (size_t)n * K1E;
    row[k] = hi; row[k + IN_DIM] = lo; row[k + 2 * IN_DIM] = hi;
}
__global__ void k_cvt_w2(const float* __restrict__ W2) {
    int i = blockIdx.x * blockDim.x + threadIdx.x;
    if (i >= F1 * ODIM) return;
    int k = i >> 6, n = i & (ODIM - 1);
    float v = W2[i];
    __nv_bfloat16 hi = __float2bfloat16(v);
    __nv_bfloat16 lo = __float2bfloat16(v - __bfloat162float(hi));
    __nv_bfloat16* row = g_w2e + (size_t)n * K2E;
    row[k] = hi; row[k + F1] = lo; row[k + 2 * F1] = hi;
}

// ================= bf16 mma.sync GEMM: C[M,N] = A[M,K] @ B[N,K]^T =================
__device__ __forceinline__ void mma16816(float* c, const uint32_t* a, const uint32_t* b) {
    asm volatile(
        "mma.sync.aligned.m16n8k16.row.col.f32.bf16.bf16.f32 "
        "{%0,%1,%2,%3}, {%4,%5,%6,%7}, {%8,%9}, {%0,%1,%2,%3};"
        : "+f"(c[0]), "+f"(c[1]), "+f"(c[2]), "+f"(c[3])
        : "r"(a[0]), "r"(a[1]), "r"(a[2]), "r"(a[3]), "r"(b[0]), "r"(b[1]));
}

template<int BM, int BN, int WM, int WN>
__global__ void __launch_bounds__(256) k_mma_gemm(
        const __nv_bfloat16* __restrict__ A,
        const __nv_bfloat16* __restrict__ B,
        float* __restrict__ C, int M, int N, int K) {
    constexpr int WT_M = BM / WM;
    constexpr int WT_N = BN / WN;
    constexpr int MF = WT_M / 16;
    constexpr int NF = WT_N / 8;
    constexpr int LDS = 40;
    constexpr int A_LD = BM * 4 / 256;
    constexpr int B_LD = BN * 4 / 256;

    __shared__ __nv_bfloat16 As[2][BM * LDS];
    __shared__ __nv_bfloat16 Bs[2][BN * LDS];

    int tid = threadIdx.x;
    int w = tid >> 5, lane = tid & 31;
    int g = lane >> 2, t4 = lane & 3;
    int wm = w / WN, wn = w % WN;
    int m0 = blockIdx.y * BM;
    int n0 = blockIdx.x * BN;
    int wrow = wm * WT_M, wcol = wn * WT_N;

    float acc[MF][NF][4];
    #pragma unroll
    for (int i = 0; i < MF; i++)
        #pragma unroll
        for (int j = 0; j < NF; j++)
            #pragma unroll
            for (int q = 0; q < 4; q++) acc[i][j][q] = 0.f;

    const uint4 zero4 = make_uint4(0, 0, 0, 0);
    int NIT = K / 32;
    uint4 pa[A_LD], pb[B_LD];

    auto load_g = [&](int k0) {
        #pragma unroll
        for (int q = 0; q < A_LD; q++) {
            int idx = tid + q * 256;
            int row = idx >> 2, seg = idx & 3;
            int gr = m0 + row;
            pa[q] = (gr < M) ? *(const uint4*)(A + (size_t)gr * K + k0 + seg * 8) : zero4;
        }
        #pragma unroll
        for (int q = 0; q < B_LD; q++) {
            int idx = tid + q * 256;
            if (B_LD * 256 == BN * 4 || idx < BN * 4) {
                int row = idx >> 2, seg = idx & 3;
                pb[q] = *(const uint4*)(B + (size_t)(n0 + row) * K + k0 + seg * 8);
            }
        }
    };
    auto store_s = [&](int buf) {
        #pragma unroll
        for (int q = 0; q < A_LD; q++) {
            int idx = tid + q * 256;
            int row = idx >> 2, seg = idx & 3;
            *(uint4*)&As[buf][row * LDS + seg * 8] = pa[q];
        }
        #pragma unroll
        for (int q = 0; q < B_LD; q++) {
            int idx = tid + q * 256;
            if (B_LD * 256 == BN * 4 || idx < BN * 4) {
                int row = idx >> 2, seg = idx & 3;
                *(uint4*)&Bs[buf][row * LDS + seg * 8] = pb[q];
            }
        }
    };

    load_g(0);
    store_s(0);
    __syncthreads();

    for (int it = 0; it < NIT; it++) {
        int buf = it & 1;
        if (it + 1 < NIT) load_g((it + 1) * 32);
        #pragma unroll
        for (int ks = 0; ks < 32; ks += 16) {
            uint32_t af[MF][4], bf[NF][2];
            #pragma unroll
            for (int mi = 0; mi < MF; mi++) {
                int r = wrow + mi * 16 + g;
                const __nv_bfloat16* base = &As[buf][0];
                af[mi][0] = *(const uint32_t*)&base[(r)     * LDS + ks + 2 * t4];
                af[mi][1] = *(const uint32_t*)&base[(r + 8) * LDS + ks + 2 * t4];
                af[mi][2] = *(const uint32_t*)&base[(r)     * LDS + ks + 2 * t4 + 8];
                af[mi][3] = *(const uint32_t*)&base[(r + 8) * LDS + ks + 2 * t4 + 8];
            }
            #pragma unroll
            for (int ni = 0; ni < NF; ni++) {
                int c = wcol + ni * 8 + g;
                const __nv_bfloat16* base = &Bs[buf][0];
                bf[ni][0] = *(const uint32_t*)&base[c * LDS + ks + 2 * t4];
                bf[ni][1] = *(const uint32_t*)&base[c * LDS + ks + 2 * t4 + 8];
            }
            #pragma unroll
            for (int mi = 0; mi < MF; mi++)
                #pragma unroll
                for (int ni = 0; ni < NF; ni++)
                    mma16816(acc[mi][ni], af[mi], bf[ni]);
        }
        __syncthreads();
        if (it + 1 < NIT) {
            store_s(buf ^ 1);
            __syncthreads();
        }
    }

    #pragma unroll
    for (int mi = 0; mi < MF; mi++) {
        #pragma unroll
        for (int ni = 0; ni < NF; ni++) {
            int r = m0 + wrow + mi * 16 + g;
            int c = n0 + wcol + ni * 8 + 2 * t4;
            if (r < M)     *(float2*)&C[(size_t)r * N + c]       = make_float2(acc[mi][ni][0], acc[mi][ni][1]);
            if (r + 8 < M) *(float2*)&C[(size_t)(r + 8) * N + c] = make_float2(acc[mi][ni][2], acc[mi][ni][3]);
        }
    }
}

// ================= attention coefficients =================
__global__ void k_attn1(const float* __restrict__ att_src, const float* __restrict__ att_dst) {
    int w = (blockIdx.x * blockDim.x + threadIdx.x) >> 5;
    int lane = threadIdx.x & 31;
    if (w >= NN * HEADS) return;
    int n = w >> 3, h = w & 7;
    const float* v = g_xl1 + n * F1 + h * HID;
    float s1 = 0.f, s2 = 0.f;
    #pragma unroll
    for (int c = lane; c < HID; c += 32) {
        float x = v[c];
        s1 += x * att_src[h * HID + c];
        s2 += x * att_dst[h * HID + c];
    }
    #pragma unroll
    for (int o = 16; o; o >>= 1) {
        s1 += __shfl_xor_sync(~0u, s1, o);
        s2 += __shfl_xor_sync(~0u, s2, o);
    }
    if (!lane) { g_asrc1[w] = s1; g_adst1[w] = s2; }
}
__global__ void k_attn2(const float* __restrict__ att_src, const float* __restrict__ att_dst) {
    int w = (blockIdx.x * blockDim.x + threadIdx.x) >> 5;
    int lane = threadIdx.x & 31;
    if (w >= NN) return;
    const float* v = g_h2 + w * ODIM;
    float s1 = v[lane] * att_src[lane] + v[lane + 32] * att_src[lane + 32];
    float s2 = v[lane] * att_dst[lane] + v[lane + 32] * att_dst[lane + 32];
    #pragma unroll
    for (int o = 16; o; o >>= 1) {
        s1 += __shfl_xor_sync(~0u, s1, o);
        s2 += __shfl_xor_sync(~0u, s2, o);
    }
    if (!lane) { g_asrc2[w] = s1; g_adst2[w] = s2; }
}

// ===== fused layer-1 segment softmax + aggregation + bias + ELU + h1e write =====
// block per dst, 256 threads = 8 warps (warp = head for phase 1).
__global__ void __launch_bounds__(256) k_smagg1(const float* __restrict__ b1) {
    int d = blockIdx.x;
    int t = threadIdx.x, lane = t & 31, w = t >> 5;
    int jb = g_rowptr[d], je = g_rowptr[d + 1];
    __shared__ float s_m[HEADS], s_rd[HEADS];
    __shared__ int   ssrc[32];
    __shared__ float salpha[32 * HEADS];

    // phase 1: warp w computes (max, 1/den) for head w
    float adst = g_adst1[d * HEADS + w];
    float m = -1e30f;
    for (int j = jb + lane; j < je; j += 32) {
        int s = g_csrsrc[j];
        float v = g_asrc1[s * HEADS + w] + adst;
        v = v > 0.f ? v : 0.2f * v;
        m = fmaxf(m, v);
    }
    #pragma unroll
    for (int o = 16; o; o >>= 1) m = fmaxf(m, __shfl_xor_sync(~0u, m, o));
    float den = 0.f;
    for (int j = jb + lane; j < je; j += 32) {
        int s = g_csrsrc[j];
        float v = g_asrc1[s * HEADS + w] + adst;
        v = v > 0.f ? v : 0.2f * v;
        den += expf(v - m);
    }
    #pragma unroll
    for (int o = 16; o; o >>= 1) den += __shfl_xor_sync(~0u, den, o);
    if (lane == 0) { s_m[w] = m; s_rd[w] = 1.f / (den + 1e-16f); }
    __syncthreads();

    // phase 2: chunked cooperative alpha + channel aggregation
    int e8 = t >> 3, h8 = t & 7;         // alpha-computation mapping (32 edges x 8 heads)
    float m2 = s_m[h8], rd2 = s_rd[h8];
    float adst8 = g_adst1[d * HEADS + h8];
    int h = t >> 5;                       // channel-group head
    const float4* xl = (const float4*)g_xl1;
    float4 acc = make_float4(0.f, 0.f, 0.f, 0.f);

    for (int j0 = jb; j0 < je; j0 += 32) {
        int cnt = min(32, je - j0);
        __syncthreads();
        if (t < cnt) ssrc[t] = g_csrsrc[j0 + t];
        __syncthreads();
        if (e8 < cnt) {
            int s = ssrc[e8];
            float v = g_asrc1[s * HEADS + h8] + adst8;
            v = v > 0.f ? v : 0.2f * v;
            salpha[e8 * HEADS + h8] = expf(v - m2) * rd2;
        }
        __syncthreads();
        for (int jj = 0; jj < cnt; jj++) {
            int s = ssrc[jj];
            float a = salpha[jj * HEADS + h];
            float4 xv = xl[(size_t)s * (F1 / 4) + t];
            acc.x += a * xv.x; acc.y += a * xv.y;
            acc.z += a * xv.z; acc.w += a * xv.w;
        }
    }

    float4 bb = ((const float4*)b1)[t];
    float v[4];
    v[0] = acc.x + bb.x; v[1] = acc.y + bb.y; v[2] = acc.z + bb.z; v[3] = acc.w + bb.w;
    #pragma unroll
    for (int q = 0; q < 4; q++) v[q] = v[q] > 0.f ? v[q] : expm1f(v[q]);
    __nv_bfloat16 hi[4], lo[4];
    #pragma unroll
    for (int q = 0; q < 4; q++) {
        hi[q] = __float2bfloat16(v[q]);
        lo[q] = __float2bfloat16(v[q] - __bfloat162float(hi[q]));
    }
    uint2 hp = *(uint2*)hi;
    uint2 lp = *(uint2*)lo;
    __nv_bfloat16* row = g_h1e + (size_t)d * K2E;
    *(uint2*)&row[4 * t]          = hp;
    *(uint2*)&row[4 * t + F1]     = hp;
    *(uint2*)&row[4 * t + 2 * F1] = lp;
}

// ===== fused layer-2 segment softmax + aggregation + bias + LayerNorm =====
// block per dst, 64 threads (= 64 channels), 2 warps.
__global__ void __launch_bounds__(64) k_smagg2ln(
        const float* __restrict__ b2, const float* __restrict__ gamma,
        const float* __restrict__ beta, float* __restrict__ out) {
    int d = blockIdx.x;
    int t = threadIdx.x, lane = t & 31, w = t >> 5;
    int jb = g_rowptr[d], je = g_rowptr[d + 1];
    __shared__ float redm[2], redd[2];
    __shared__ int   ssrc[64];
    __shared__ float salpha[64];

    float adst = g_adst2[d];
    float m = -1e30f;
    for (int j = jb + t; j < je; j += 64) {
        float v = g_asrc2[g_csrsrc[j]] + adst;
        v = v > 0.f ? v : 0.2f * v;
        m = fmaxf(m, v);
    }
    #pragma unroll
    for (int o = 16; o; o >>= 1) m = fmaxf(m, __shfl_xor_sync(~0u, m, o));
    if (lane == 0) redm[w] = m;
    __syncthreads();
    m = fmaxf(redm[0], redm[1]);
    float den = 0.f;
    for (int j = jb + t; j < je; j += 64) {
        float v = g_asrc2[g_csrsrc[j]] + adst;
        v = v > 0.f ? v : 0.2f * v;
        den += expf(v - m);
    }
    #pragma unroll
    for (int o = 16; o; o >>= 1) den += __shfl_xor_sync(~0u, den, o);
    if (lane == 0) redd[w] = den;
    __syncthreads();
    float rd = 1.f / (redd[0] + redd[1] + 1e-16f);

    float acc = 0.f;
    for (int j0 = jb; j0 < je; j0 += 64) {
        int cnt = min(64, je - j0);
        __syncthreads();
        if (t < cnt) {
            int s = g_csrsrc[j0 + t];
            ssrc[t] = s;
            float v = g_asrc2[s] + adst;
            v = v > 0.f ? v : 0.2f * v;
            salpha[t] = expf(v - m) * rd;
        }
        __syncthreads();
        for (int jj = 0; jj < cnt; jj++)
            acc += salpha[jj] * g_h2[(size_t)ssrc[jj] * ODIM + t];
    }

    // bias + LayerNorm
    float val = acc + b2[t];
    float s = val;
    #pragma unroll
    for (int o = 16; o; o >>= 1) s += __shfl_xor_sync(~0u, s, o);
    __syncthreads();
    if (lane == 0) redd[w] = s;
    __syncthreads();
    float mu = (redd[0] + redd[1]) * (1.f / 64.f);
    float dv = val - mu;
    float q = dv * dv;
    #pragma unroll
    for (int o = 16; o; o >>= 1) q += __shfl_xor_sync(~0u, q, o);
    __syncthreads();
    if (lane == 0) redm[w] = q;
    __syncthreads();
    float inv = rsqrtf((redm[0] + redm[1]) * (1.f / 64.f) + 1e-5f);
    out[(size_t)d * ODIM + t] = dv * inv * gamma[t] + beta[t];
}

// ================= launch =================
extern "C" void kernel_launch(void* const* d_in, const int* in_sizes, int n_in,
                              void* d_out, int out_size) {
    const float* x     = (const float*)d_in[0];
    const int*   ei    = (const int*)  d_in[1];
    const float* W1    = (const float*)d_in[2];
    const float* as1   = (const float*)d_in[3];
    const float* ad1   = (const float*)d_in[4];
    const float* b1    = (const float*)d_in[5];
    const float* W2    = (const float*)d_in[6];
    const float* as2   = (const float*)d_in[7];
    const float* ad2   = (const float*)d_in[8];
    const float* b2    = (const float*)d_in[9];
    const float* gamma = (const float*)d_in[10];
    const float* beta  = (const float*)d_in[11];
    float* out = (float*)d_out;

    __nv_bfloat16 *xe, *w1e, *h1e, *w2e;
    float *xl1, *h2;
    cudaGetSymbolAddress((void**)&xe,  g_xe);
    cudaGetSymbolAddress((void**)&w1e, g_w1e);
    cudaGetSymbolAddress((void**)&h1e, g_h1e);
    cudaGetSymbolAddress((void**)&w2e, g_w2e);
    cudaGetSymbolAddress((void**)&xl1, g_xl1);
    cudaGetSymbolAddress((void**)&h2,  g_h2);

    // persistent side stream + fork/join events (host-side handles only; the
    // captured WORK is identical on every call)
    static cudaStream_t s_side = nullptr;
    static cudaEvent_t  s_ev0 = nullptr, s_ev1 = nullptr;
    if (!s_side) {
        cudaStreamCreateWithFlags(&s_side, cudaStreamNonBlocking);
        cudaEventCreateWithFlags(&s_ev0, cudaEventDisableTiming);
        cudaEventCreateWithFlags(&s_ev1, cudaEventDisableTiming);
    }

    // fork: side stream does CSR build + cvt_w2 concurrently with GEMM1 path
    cudaEventRecord(s_ev0, 0);
    cudaStreamWaitEvent(s_side, s_ev0, 0);
    k_csr_init<<<(NN + 255) / 256, 256, 0, s_side>>>();
    k_deg<<<(ET + 255) / 256, 256, 0, s_side>>>(ei);
    k_scan<<<1, 1024, 0, s_side>>>();
    k_scatter<<<(ET + 255) / 256, 256, 0, s_side>>>(ei);
    k_cvt_w2<<<(F1 * ODIM + 255) / 256, 256, 0, s_side>>>(W2);
    cudaEventRecord(s_ev1, s_side);

    // main path
    k_cvt_x<<<(NN * IN_DIM + 255) / 256, 256>>>(x);
    k_cvt_w1<<<(IN_DIM * F1 + 255) / 256, 256>>>(W1);
    {
        dim3 g(F1 / 128, (NN + 127) / 128);
        k_mma_gemm<128, 128, 2, 4><<<g, 256>>>(xe, w1e, xl1, NN, F1, K1E);
    }
    k_attn1<<<(NN * HEADS * 32 + 255) / 256, 256>>>(as1, ad1);

    // join: CSR + cvt_w2 must be done before aggregation / GEMM2
    cudaStreamWaitEvent(0, s_ev1, 0);

    k_smagg1<<<NN, 256>>>(b1);
    {
        dim3 g(ODIM / 64, (NN + 63) / 64);
        k_mma_gemm<64, 64, 2, 4><<<g, 256>>>(h1e, w2e, h2, NN, ODIM, K2E);
    }
    k_attn2<<<(NN * 32 + 255) / 256, 256>>>(as2, ad2);
    k_smagg2ln<<<NN, 64>>>(b2, gamma, beta, out);
}

// round 7
// speedup vs baseline: 3.0767x; 1.0880x over previous
#include <cuda_runtime.h>
#include <cuda_bf16.h>
#include <math.h>
#include <stdint.h>

#define NN      10000
#define NE      160000
#define ET      170000
#define IN_DIM  256
#define HID     128
#define HEADS   8
#define F1      1024
#define ODIM    64

#define K1E     (3 * IN_DIM)   // 768
#define K2E     (3 * F1)       // 3072
#define K2A     (2 * F1)       // 2048 : de-duplicated A width for GEMM2

// ================= scratch (device globals; no allocation) =================
__device__ float g_xl1  [NN * F1];
__device__ float g_asrc1[NN * HEADS];
__device__ float g_adst1[NN * HEADS];
__device__ float g_h2   [NN * ODIM];
__device__ float g_asrc2[NN];
__device__ float g_adst2[NN];
__device__ int g_deg   [NN];
__device__ int g_cursor[NN];
__device__ int g_rowptr[NN + 1];
__device__ int g_csrsrc[ET];
__device__ __nv_bfloat16 g_xe  [NN * K1E];     // [hi | hi | lo]
__device__ __nv_bfloat16 g_w1e [F1 * K1E];     // [hi | lo | hi]
__device__ __nv_bfloat16 g_h1e [NN * K2A];     // [hi | lo]   (A-side, k-remapped)
__device__ __nv_bfloat16 g_w2e [ODIM * K2E];   // [hi | lo | hi]

// ================= CSR build =================
__device__ __forceinline__ void edge_sd(const int* __restrict__ ei, int e, int& s, int& d) {
    if (e < NE) { s = ei[e]; d = ei[NE + e]; }
    else        { s = e - NE; d = e - NE; }
}
__global__ void k_csr_init() {
    int i = blockIdx.x * blockDim.x + threadIdx.x;
    if (i < NN) { g_deg[i] = 0; g_cursor[i] = 0; }
}
__global__ void k_deg(const int* __restrict__ ei) {
    int e = blockIdx.x * blockDim.x + threadIdx.x;
    if (e >= ET) return;
    int d = (e < NE) ? ei[NE + e] : (e - NE);
    atomicAdd(&g_deg[d], 1);
}
__global__ void k_scan() {
    __shared__ int warpsum[32];
    __shared__ int carry_s;
    int t = threadIdx.x, lane = t & 31, w = t >> 5;
    if (t == 0) carry_s = 0;
    __syncthreads();
    for (int base = 0; base < NN; base += 1024) {
        int i = base + t;
        int x = (i < NN) ? g_deg[i] : 0;
        #pragma unroll
        for (int o = 1; o < 32; o <<= 1) {
            int y = __shfl_up_sync(~0u, x, o);
            if (lane >= o) x += y;
        }
        if (lane == 31) warpsum[w] = x;
        __syncthreads();
        if (w == 0) {
            int s = warpsum[lane];
            #pragma unroll
            for (int o = 1; o < 32; o <<= 1) {
                int y = __shfl_up_sync(~0u, s, o);
                if (lane >= o) s += y;
            }
            warpsum[lane] = s;
        }
        __syncthreads();
        int incl = x + (w ? warpsum[w - 1] : 0) + carry_s;
        if (i < NN) g_rowptr[i + 1] = incl;
        __syncthreads();
        if (t == 1023) carry_s = incl;
        __syncthreads();
    }
    if (threadIdx.x == 0) g_rowptr[0] = 0;
}
__global__ void k_scatter(const int* __restrict__ ei) {
    int e = blockIdx.x * blockDim.x + threadIdx.x;
    if (e >= ET) return;
    int s, d; edge_sd(ei, e, s, d);
    int pos = atomicAdd(&g_cursor[d], 1);
    g_csrsrc[g_rowptr[d] + pos] = s;
}

// ================= hi/lo-extended conversion (x + W1 fused) =================
__global__ void k_cvt1(const float* __restrict__ x, const float* __restrict__ W1) {
    int i = blockIdx.x * blockDim.x + threadIdx.x;
    if (i < NN * IN_DIM) {
        float v = x[i];
        __nv_bfloat16 hi = __float2bfloat16(v);
        __nv_bfloat16 lo = __float2bfloat16(v - __bfloat162float(hi));
        int r = i >> 8, k = i & (IN_DIM - 1);
        __nv_bfloat16* row = g_xe + (size_t)r * K1E;
        row[k] = hi; row[k + IN_DIM] = hi; row[k + 2 * IN_DIM] = lo;
        return;
    }
    int j = i - NN * IN_DIM;
    if (j < IN_DIM * F1) {
        int k = j >> 10, n = j & (F1 - 1);
        float v = W1[j];
        __nv_bfloat16 hi = __float2bfloat16(v);
        __nv_bfloat16 lo = __float2bfloat16(v - __bfloat162float(hi));
        __nv_bfloat16* row = g_w1e + (size_t)n * K1E;
        row[k] = hi; row[k + IN_DIM] = lo; row[k + 2 * IN_DIM] = hi;
    }
}
__global__ void k_cvt_w2(const float* __restrict__ W2) {
    int i = blockIdx.x * blockDim.x + threadIdx.x;
    if (i >= F1 * ODIM) return;
    int k = i >> 6, n = i & (ODIM - 1);
    float v = W2[i];
    __nv_bfloat16 hi = __float2bfloat16(v);
    __nv_bfloat16 lo = __float2bfloat16(v - __bfloat162float(hi));
    __nv_bfloat16* row = g_w2e + (size_t)n * K2E;
    row[k] = hi; row[k + F1] = lo; row[k + 2 * F1] = hi;
}

// ================= bf16 mma.sync GEMM: C[M,N] = A[M,K'] @ B[N,K]^T =================
// FOLD=0: A width = K. FOLD=F: A width = 2F, A col = k<F ? k : k-F (K=3F).
// Optional fused attention epilogue: out_s[r*nh+head] = sum_c C[r,c]*att_src[gcol],
// att flat index = global column.
__device__ __forceinline__ void mma16816(float* c, const uint32_t* a, const uint32_t* b) {
    asm volatile(
        "mma.sync.aligned.m16n8k16.row.col.f32.bf16.bf16.f32 "
        "{%0,%1,%2,%3}, {%4,%5,%6,%7}, {%8,%9}, {%0,%1,%2,%3};"
        : "+f"(c[0]), "+f"(c[1]), "+f"(c[2]), "+f"(c[3])
        : "r"(a[0]), "r"(a[1]), "r"(a[2]), "r"(a[3]), "r"(b[0]), "r"(b[1]));
}

template<int BM, int BN, int WM, int WN, int FOLD>
__global__ void __launch_bounds__(256) k_mma_gemm(
        const __nv_bfloat16* __restrict__ A,
        const __nv_bfloat16* __restrict__ B,
        float* __restrict__ C, int M, int N, int K,
        const float* __restrict__ att_src, const float* __restrict__ att_dst,
        float* __restrict__ out_s, float* __restrict__ out_d, int nh) {
    constexpr int WT_M = BM / WM;
    constexpr int WT_N = BN / WN;
    constexpr int MF = WT_M / 16;
    constexpr int NF = WT_N / 8;
    constexpr int LDS = 40;
    constexpr int A_LD = BM * 4 / 256;
    constexpr int B_LD = BN * 4 / 256;

    __shared__ __nv_bfloat16 As[2][BM * LDS];
    __shared__ __nv_bfloat16 Bs[2][BN * LDS];

    int tid = threadIdx.x;
    int w = tid >> 5, lane = tid & 31;
    int g = lane >> 2, t4 = lane & 3;
    int wm = w / WN, wn = w % WN;
    int m0 = blockIdx.y * BM;
    int n0 = blockIdx.x * BN;
    int wrow = wm * WT_M, wcol = wn * WT_N;
    int lda = FOLD ? 2 * FOLD : K;

    float acc[MF][NF][4];
    #pragma unroll
    for (int i = 0; i < MF; i++)
        #pragma unroll
        for (int j = 0; j < NF; j++)
            #pragma unroll
            for (int q = 0; q < 4; q++) acc[i][j][q] = 0.f;

    const uint4 zero4 = make_uint4(0, 0, 0, 0);
    int NIT = K / 32;
    uint4 pa[A_LD], pb[B_LD];

    auto load_g = [&](int k0) {
        int k0a = (FOLD && k0 >= FOLD) ? k0 - FOLD : k0;
        #pragma unroll
        for (int q = 0; q < A_LD; q++) {
            int idx = tid + q * 256;
            int row = idx >> 2, seg = idx & 3;
            int gr = m0 + row;
            pa[q] = (gr < M) ? *(const uint4*)(A + (size_t)gr * lda + k0a + seg * 8) : zero4;
        }
        #pragma unroll
        for (int q = 0; q < B_LD; q++) {
            int idx = tid + q * 256;
            if (B_LD * 256 == BN * 4 || idx < BN * 4) {
                int row = idx >> 2, seg = idx & 3;
                pb[q] = *(const uint4*)(B + (size_t)(n0 + row) * K + k0 + seg * 8);
            }
        }
    };
    auto store_s = [&](int buf) {
        #pragma unroll
        for (int q = 0; q < A_LD; q++) {
            int idx = tid + q * 256;
            int row = idx >> 2, seg = idx & 3;
            *(uint4*)&As[buf][row * LDS + seg * 8] = pa[q];
        }
        #pragma unroll
        for (int q = 0; q < B_LD; q++) {
            int idx = tid + q * 256;
            if (B_LD * 256 == BN * 4 || idx < BN * 4) {
                int row = idx >> 2, seg = idx & 3;
                *(uint4*)&Bs[buf][row * LDS + seg * 8] = pb[q];
            }
        }
    };

    load_g(0);
    store_s(0);
    __syncthreads();

    for (int it = 0; it < NIT; it++) {
        int buf = it & 1;
        if (it + 1 < NIT) load_g((it + 1) * 32);
        #pragma unroll
        for (int ks = 0; ks < 32; ks += 16) {
            uint32_t af[MF][4], bf[NF][2];
            #pragma unroll
            for (int mi = 0; mi < MF; mi++) {
                int r = wrow + mi * 16 + g;
                const __nv_bfloat16* base = &As[buf][0];
                af[mi][0] = *(const uint32_t*)&base[(r)     * LDS + ks + 2 * t4];
                af[mi][1] = *(const uint32_t*)&base[(r + 8) * LDS + ks + 2 * t4];
                af[mi][2] = *(const uint32_t*)&base[(r)     * LDS + ks + 2 * t4 + 8];
                af[mi][3] = *(const uint32_t*)&base[(r + 8) * LDS + ks + 2 * t4 + 8];
            }
            #pragma unroll
            for (int ni = 0; ni < NF; ni++) {
                int c = wcol + ni * 8 + g;
                const __nv_bfloat16* base = &Bs[buf][0];
                bf[ni][0] = *(const uint32_t*)&base[c * LDS + ks + 2 * t4];
                bf[ni][1] = *(const uint32_t*)&base[c * LDS + ks + 2 * t4 + 8];
            }
            #pragma unroll
            for (int mi = 0; mi < MF; mi++)
                #pragma unroll
                for (int ni = 0; ni < NF; ni++)
                    mma16816(acc[mi][ni], af[mi], bf[ni]);
        }
        __syncthreads();
        if (it + 1 < NIT) {
            store_s(buf ^ 1);
            __syncthreads();
        }
    }

    // ---- fused attention-coefficient epilogue ----
    if (att_src) {
        float* s1a = (float*)&As[0][0];        // reuse smem (safe: post-loop barrier)
        float* s2a = s1a + BM;
        if (tid < BM) { s1a[tid] = 0.f; s2a[tid] = 0.f; }
        __syncthreads();
        float asr[NF][2], adr[NF][2];
        #pragma unroll
        for (int ni = 0; ni < NF; ni++)
            #pragma unroll
            for (int q = 0; q < 2; q++) {
                int gc = n0 + wcol + ni * 8 + 2 * t4 + q;
                asr[ni][q] = att_src[gc];
                adr[ni][q] = att_dst[gc];
            }
        #pragma unroll
        for (int mi = 0; mi < MF; mi++) {
            #pragma unroll
            for (int half = 0; half < 2; half++) {
                float p1 = 0.f, p2 = 0.f;
                #pragma unroll
                for (int ni = 0; ni < NF; ni++)
                    #pragma unroll
                    for (int q = 0; q < 2; q++) {
                        float v = acc[mi][ni][half * 2 + q];
                        p1 += v * asr[ni][q];
                        p2 += v * adr[ni][q];
                    }
                p1 += __shfl_xor_sync(~0u, p1, 1); p1 += __shfl_xor_sync(~0u, p1, 2);
                p2 += __shfl_xor_sync(~0u, p2, 1); p2 += __shfl_xor_sync(~0u, p2, 2);
                if (t4 == 0) {
                    int r = wrow + mi * 16 + half * 8 + g;
                    atomicAdd(&s1a[r], p1);
                    atomicAdd(&s2a[r], p2);
                }
            }
        }
        __syncthreads();
        int head = blockIdx.x % nh;
        if (tid < BM && m0 + tid < M) {
            out_s[(size_t)(m0 + tid) * nh + head] = s1a[tid];
            out_d[(size_t)(m0 + tid) * nh + head] = s2a[tid];
        }
    }

    // ---- C store ----
    #pragma unroll
    for (int mi = 0; mi < MF; mi++) {
        #pragma unroll
        for (int ni = 0; ni < NF; ni++) {
            int r = m0 + wrow + mi * 16 + g;
            int c = n0 + wcol + ni * 8 + 2 * t4;
            if (r < M)     *(float2*)&C[(size_t)r * N + c]       = make_float2(acc[mi][ni][0], acc[mi][ni][1]);
            if (r + 8 < M) *(float2*)&C[(size_t)(r + 8) * N + c] = make_float2(acc[mi][ni][2], acc[mi][ni][3]);
        }
    }
}

// ===== fused layer-1 segment softmax + aggregation + bias + ELU + h1e [hi|lo] =====
__global__ void __launch_bounds__(256) k_smagg1(const float* __restrict__ b1) {
    int d = blockIdx.x;
    int t = threadIdx.x, lane = t & 31, w = t >> 5;
    int jb = g_rowptr[d], je = g_rowptr[d + 1];
    __shared__ float s_m[HEADS], s_rd[HEADS];
    __shared__ int   ssrc[32];
    __shared__ float salpha[32 * HEADS];

    float adst = g_adst1[d * HEADS + w];
    float m = -1e30f;
    for (int j = jb + lane; j < je; j += 32) {
        int s = g_csrsrc[j];
        float v = g_asrc1[s * HEADS + w] + adst;
        v = v > 0.f ? v : 0.2f * v;
        m = fmaxf(m, v);
    }
    #pragma unroll
    for (int o = 16; o; o >>= 1) m = fmaxf(m, __shfl_xor_sync(~0u, m, o));
    float den = 0.f;
    for (int j = jb + lane; j < je; j += 32) {
        int s = g_csrsrc[j];
        float v = g_asrc1[s * HEADS + w] + adst;
        v = v > 0.f ? v : 0.2f * v;
        den += expf(v - m);
    }
    #pragma unroll
    for (int o = 16; o; o >>= 1) den += __shfl_xor_sync(~0u, den, o);
    if (lane == 0) { s_m[w] = m; s_rd[w] = 1.f / (den + 1e-16f); }
    __syncthreads();

    int e8 = t >> 3, h8 = t & 7;
    float m2 = s_m[h8], rd2 = s_rd[h8];
    float adst8 = g_adst1[d * HEADS + h8];
    int h = t >> 5;
    const float4* xl = (const float4*)g_xl1;
    float4 acc = make_float4(0.f, 0.f, 0.f, 0.f);

    for (int j0 = jb; j0 < je; j0 += 32) {
        int cnt = min(32, je - j0);
        __syncthreads();
        if (t < cnt) ssrc[t] = g_csrsrc[j0 + t];
        __syncthreads();
        if (e8 < cnt) {
            int s = ssrc[e8];
            float v = g_asrc1[s * HEADS + h8] + adst8;
            v = v > 0.f ? v : 0.2f * v;
            salpha[e8 * HEADS + h8] = expf(v - m2) * rd2;
        }
        __syncthreads();
        for (int jj = 0; jj < cnt; jj++) {
            int s = ssrc[jj];
            float a = salpha[jj * HEADS + h];
            float4 xv = xl[(size_t)s * (F1 / 4) + t];
            acc.x += a * xv.x; acc.y += a * xv.y;
            acc.z += a * xv.z; acc.w += a * xv.w;
        }
    }

    float4 bb = ((const float4*)b1)[t];
    float v[4];
    v[0] = acc.x + bb.x; v[1] = acc.y + bb.y; v[2] = acc.z + bb.z; v[3] = acc.w + bb.w;
    #pragma unroll
    for (int q = 0; q < 4; q++) v[q] = v[q] > 0.f ? v[q] : expm1f(v[q]);
    __nv_bfloat16 hi[4], lo[4];
    #pragma unroll
    for (int q = 0; q < 4; q++) {
        hi[q] = __float2bfloat16(v[q]);
        lo[q] = __float2bfloat16(v[q] - __bfloat162float(hi[q]));
    }
    __nv_bfloat16* row = g_h1e + (size_t)d * K2A;
    *(uint2*)&row[4 * t]      = *(uint2*)hi;
    *(uint2*)&row[4 * t + F1] = *(uint2*)lo;
}

// ===== fused layer-2 segment softmax + aggregation + bias + LayerNorm =====
__global__ void __launch_bounds__(64) k_smagg2ln(
        const float* __restrict__ b2, const float* __restrict__ gamma,
        const float* __restrict__ beta, float* __restrict__ out) {
    int d = blockIdx.x;
    int t = threadIdx.x, lane = t & 31, w = t >> 5;
    int jb = g_rowptr[d], je = g_rowptr[d + 1];
    __shared__ float redm[2], redd[2];
    __shared__ int   ssrc[64];
    __shared__ float salpha[64];

    float adst = g_adst2[d];
    float m = -1e30f;
    for (int j = jb + t; j < je; j += 64) {
        float v = g_asrc2[g_csrsrc[j]] + adst;
        v = v > 0.f ? v : 0.2f * v;
        m = fmaxf(m, v);
    }
    #pragma unroll
    for (int o = 16; o; o >>= 1) m = fmaxf(m, __shfl_xor_sync(~0u, m, o));
    if (lane == 0) redm[w] = m;
    __syncthreads();
    m = fmaxf(redm[0], redm[1]);
    float den = 0.f;
    for (int j = jb + t; j < je; j += 64) {
        float v = g_asrc2[g_csrsrc[j]] + adst;
        v = v > 0.f ? v : 0.2f * v;
        den += expf(v - m);
    }
    #pragma unroll
    for (int o = 16; o; o >>= 1) den += __shfl_xor_sync(~0u, den, o);
    if (lane == 0) redd[w] = den;
    __syncthreads();
    float rd = 1.f / (redd[0] + redd[1] + 1e-16f);

    float acc = 0.f;
    for (int j0 = jb; j0 < je; j0 += 64) {
        int cnt = min(64, je - j0);
        __syncthreads();
        if (t < cnt) {
            int s = g_csrsrc[j0 + t];
            ssrc[t] = s;
            float v = g_asrc2[s] + adst;
            v = v > 0.f ? v : 0.2f * v;
            salpha[t] = expf(v - m) * rd;
        }
        __syncthreads();
        for (int jj = 0; jj < cnt; jj++)
            acc += salpha[jj] * g_h2[(size_t)ssrc[jj] * ODIM + t];
    }

    float val = acc + b2[t];
    float s = val;
    #pragma unroll
    for (int o = 16; o; o >>= 1) s += __shfl_xor_sync(~0u, s, o);
    __syncthreads();
    if (lane == 0) redd[w] = s;
    __syncthreads();
    float mu = (redd[0] + redd[1]) * (1.f / 64.f);
    float dv = val - mu;
    float q = dv * dv;
    #pragma unroll
    for (int o = 16; o; o >>= 1) q += __shfl_xor_sync(~0u, q, o);
    __syncthreads();
    if (lane == 0) redm[w] = q;
    __syncthreads();
    float inv = rsqrtf((redm[0] + redm[1]) * (1.f / 64.f) + 1e-5f);
    out[(size_t)d * ODIM + t] = dv * inv * gamma[t] + beta[t];
}

// ================= launch =================
extern "C" void kernel_launch(void* const* d_in, const int* in_sizes, int n_in,
                              void* d_out, int out_size) {
    const float* x     = (const float*)d_in[0];
    const int*   ei    = (const int*)  d_in[1];
    const float* W1    = (const float*)d_in[2];
    const float* as1   = (const float*)d_in[3];
    const float* ad1   = (const float*)d_in[4];
    const float* b1    = (const float*)d_in[5];
    const float* W2    = (const float*)d_in[6];
    const float* as2   = (const float*)d_in[7];
    const float* ad2   = (const float*)d_in[8];
    const float* b2    = (const float*)d_in[9];
    const float* gamma = (const float*)d_in[10];
    const float* beta  = (const float*)d_in[11];
    float* out = (float*)d_out;

    __nv_bfloat16 *xe, *w1e, *h1e, *w2e;
    float *xl1, *h2, *asrc1, *adst1, *asrc2, *adst2;
    cudaGetSymbolAddress((void**)&xe,    g_xe);
    cudaGetSymbolAddress((void**)&w1e,   g_w1e);
    cudaGetSymbolAddress((void**)&h1e,   g_h1e);
    cudaGetSymbolAddress((void**)&w2e,   g_w2e);
    cudaGetSymbolAddress((void**)&xl1,   g_xl1);
    cudaGetSymbolAddress((void**)&h2,    g_h2);
    cudaGetSymbolAddress((void**)&asrc1, g_asrc1);
    cudaGetSymbolAddress((void**)&adst1, g_adst1);
    cudaGetSymbolAddress((void**)&asrc2, g_asrc2);
    cudaGetSymbolAddress((void**)&adst2, g_adst2);

    static cudaStream_t s_side = nullptr;
    static cudaEvent_t  s_ev0 = nullptr, s_ev1 = nullptr;
    if (!s_side) {
        cudaStreamCreateWithFlags(&s_side, cudaStreamNonBlocking);
        cudaEventCreateWithFlags(&s_ev0, cudaEventDisableTiming);
        cudaEventCreateWithFlags(&s_ev1, cudaEventDisableTiming);
    }

    // fork: CSR build + cvt_w2 on side stream
    cudaEventRecord(s_ev0, 0);
    cudaStreamWaitEvent(s_side, s_ev0, 0);
    k_csr_init<<<(NN + 255) / 256, 256, 0, s_side>>>();
    k_deg<<<(ET + 255) / 256, 256, 0, s_side>>>(ei);
    k_scan<<<1, 1024, 0, s_side>>>();
    k_scatter<<<(ET + 255) / 256, 256, 0, s_side>>>(ei);
    k_cvt_w2<<<(F1 * ODIM + 255) / 256, 256, 0, s_side>>>(W2);
    cudaEventRecord(s_ev1, s_side);

    // main path
    k_cvt1<<<(NN * IN_DIM + IN_DIM * F1 + 255) / 256, 256>>>(x, W1);
    {   // GEMM1 + fused attn1 (grid.x = 8 = heads)
        dim3 g(F1 / 128, (NN + 127) / 128);
        k_mma_gemm<128, 128, 2, 4, 0><<<g, 256>>>(xe, w1e, xl1, NN, F1, K1E,
                                                  as1, ad1, asrc1, adst1, HEADS);
    }

    cudaStreamWaitEvent(0, s_ev1, 0);

    k_smagg1<<<NN, 256>>>(b1);
    {   // GEMM2 + fused attn2 (A k-folded [hi|lo])
        dim3 g(1, (NN + 63) / 64);
        k_mma_gemm<64, 64, 2, 4, F1><<<g, 256>>>(h1e, w2e, h2, NN, ODIM, K2E,
                                                 as2, ad2, asrc2, adst2, 1);
    }
    k_smagg2ln<<<NN, 64>>>(b2, gamma, beta, out);
}

// round 8
// speedup vs baseline: 3.0771x; 1.0001x over previous
#include <cuda_runtime.h>
#include <cuda_bf16.h>
#include <math.h>
#include <stdint.h>

#define NN      10000
#define NE      160000
#define ET      170000
#define IN_DIM  256
#define HID     128
#define HEADS   8
#define F1      1024
#define ODIM    64

#define K1E     (3 * IN_DIM)   // 768
#define K2E     (3 * F1)       // 3072
#define K2A     (2 * F1)       // 2048 : de-duplicated A width for GEMM2

// ================= scratch (device globals; no allocation) =================
__device__ float g_xl1  [NN * F1];
__device__ float g_asrc1[NN * HEADS];
__device__ float g_adst1[NN * HEADS];
__device__ float g_h2   [NN * ODIM];
__device__ float g_asrc2[NN];
__device__ float g_adst2[NN];
__device__ int g_deg   [NN];
__device__ int g_cursor[NN];
__device__ int g_rowptr[NN + 1];
__device__ int g_csrsrc[ET];
__device__ __nv_bfloat16 g_xe  [NN * K1E];     // [hi | hi | lo]
__device__ __nv_bfloat16 g_w1e [F1 * K1E];     // [hi | lo | hi]
__device__ __nv_bfloat16 g_h1e [NN * K2A];     // [hi | lo]
__device__ __nv_bfloat16 g_w2e [ODIM * K2E];   // [hi | lo | hi]

__device__ __forceinline__ uint32_t smem_u32(const void* p) {
    uint32_t a;
    asm("{ .reg .u64 t; cvta.to.shared.u64 t, %1; cvt.u32.u64 %0, t; }" : "=r"(a) : "l"(p));
    return a;
}
__device__ __forceinline__ void ldmatrix_x4(uint32_t* r, uint32_t addr) {
    asm volatile("ldmatrix.sync.aligned.m8n8.x4.shared.b16 {%0,%1,%2,%3}, [%4];"
        : "=r"(r[0]), "=r"(r[1]), "=r"(r[2]), "=r"(r[3]) : "r"(addr));
}

// ================= CSR build =================
__device__ __forceinline__ void edge_sd(const int* __restrict__ ei, int e, int& s, int& d) {
    if (e < NE) { s = ei[e]; d = ei[NE + e]; }
    else        { s = e - NE; d = e - NE; }
}
__global__ void k_csr_init() {
    int i = blockIdx.x * blockDim.x + threadIdx.x;
    if (i < NN) { g_deg[i] = 0; g_cursor[i] = 0; }
}
__global__ void k_deg(const int* __restrict__ ei) {
    int e = blockIdx.x * blockDim.x + threadIdx.x;
    if (e >= ET) return;
    int d = (e < NE) ? ei[NE + e] : (e - NE);
    atomicAdd(&g_deg[d], 1);
}
__global__ void k_scan() {
    __shared__ int warpsum[32];
    __shared__ int carry_s;
    int t = threadIdx.x, lane = t & 31, w = t >> 5;
    if (t == 0) carry_s = 0;
    __syncthreads();
    for (int base = 0; base < NN; base += 1024) {
        int i = base + t;
        int x = (i < NN) ? g_deg[i] : 0;
        #pragma unroll
        for (int o = 1; o < 32; o <<= 1) {
            int y = __shfl_up_sync(~0u, x, o);
            if (lane >= o) x += y;
        }
        if (lane == 31) warpsum[w] = x;
        __syncthreads();
        if (w == 0) {
            int s = warpsum[lane];
            #pragma unroll
            for (int o = 1; o < 32; o <<= 1) {
                int y = __shfl_up_sync(~0u, s, o);
                if (lane >= o) s += y;
            }
            warpsum[lane] = s;
        }
        __syncthreads();
        int incl = x + (w ? warpsum[w - 1] : 0) + carry_s;
        if (i < NN) g_rowptr[i + 1] = incl;
        __syncthreads();
        if (t == 1023) carry_s = incl;
        __syncthreads();
    }
    if (threadIdx.x == 0) g_rowptr[0] = 0;
}
__global__ void k_scatter(const int* __restrict__ ei) {
    int e = blockIdx.x * blockDim.x + threadIdx.x;
    if (e >= ET) return;
    int s, d; edge_sd(ei, e, s, d);
    int pos = atomicAdd(&g_cursor[d], 1);
    g_csrsrc[g_rowptr[d] + pos] = s;
}

// ================= hi/lo-extended conversion =================
__global__ void k_cvt1(const float* __restrict__ x, const float* __restrict__ W1) {
    int i = blockIdx.x * blockDim.x + threadIdx.x;
    if (i < NN * IN_DIM) {
        float v = x[i];
        __nv_bfloat16 hi = __float2bfloat16(v);
        __nv_bfloat16 lo = __float2bfloat16(v - __bfloat162float(hi));
        int r = i >> 8, k = i & (IN_DIM - 1);
        __nv_bfloat16* row = g_xe + (size_t)r * K1E;
        row[k] = hi; row[k + IN_DIM] = hi; row[k + 2 * IN_DIM] = lo;
        return;
    }
    int j = i - NN * IN_DIM;
    if (j < IN_DIM * F1) {
        int k = j >> 10, n = j & (F1 - 1);
        float v = W1[j];
        __nv_bfloat16 hi = __float2bfloat16(v);
        __nv_bfloat16 lo = __float2bfloat16(v - __bfloat162float(hi));
        __nv_bfloat16* row = g_w1e + (size_t)n * K1E;
        row[k] = hi; row[k + IN_DIM] = lo; row[k + 2 * IN_DIM] = hi;
    }
}
__global__ void k_cvt_w2(const float* __restrict__ W2) {
    int i = blockIdx.x * blockDim.x + threadIdx.x;
    if (i >= F1 * ODIM) return;
    int k = i >> 6, n = i & (ODIM - 1);
    float v = W2[i];
    __nv_bfloat16 hi = __float2bfloat16(v);
    __nv_bfloat16 lo = __float2bfloat16(v - __bfloat162float(hi));
    __nv_bfloat16* row = g_w2e + (size_t)n * K2E;
    row[k] = hi; row[k + F1] = lo; row[k + 2 * F1] = hi;
}

// ================= bf16 mma.sync GEMM with ldmatrix fragments =================
__device__ __forceinline__ void mma16816(float* c, const uint32_t* a, const uint32_t* b) {
    asm volatile(
        "mma.sync.aligned.m16n8k16.row.col.f32.bf16.bf16.f32 "
        "{%0,%1,%2,%3}, {%4,%5,%6,%7}, {%8,%9}, {%0,%1,%2,%3};"
        : "+f"(c[0]), "+f"(c[1]), "+f"(c[2]), "+f"(c[3])
        : "r"(a[0]), "r"(a[1]), "r"(a[2]), "r"(a[3]), "r"(b[0]), "r"(b[1]));
}

template<int BM, int BN, int WM, int WN, int FOLD>
__global__ void __launch_bounds__(256) k_mma_gemm(
        const __nv_bfloat16* __restrict__ A,
        const __nv_bfloat16* __restrict__ B,
        float* __restrict__ C, int M, int N, int K,
        const float* __restrict__ att_src, const float* __restrict__ att_dst,
        float* __restrict__ out_s, float* __restrict__ out_d, int nh) {
    constexpr int WT_M = BM / WM;
    constexpr int WT_N = BN / WN;
    constexpr int MF = WT_M / 16;
    constexpr int NF = WT_N / 8;
    constexpr int LDS = 40;
    constexpr int A_LD = BM * 4 / 256;
    constexpr int B_LD = BN * 4 / 256;

    __shared__ __nv_bfloat16 As[2][BM * LDS];
    __shared__ __nv_bfloat16 Bs[2][BN * LDS];

    int tid = threadIdx.x;
    int w = tid >> 5, lane = tid & 31;
    int g = lane >> 2, t4 = lane & 3;
    int wm = w / WN, wn = w % WN;
    int m0 = blockIdx.y * BM;
    int n0 = blockIdx.x * BN;
    int wrow = wm * WT_M, wcol = wn * WT_N;
    int lda = FOLD ? 2 * FOLD : K;

    // ldmatrix per-thread addressing
    int arow = lane & 15;                 // A: row offset within 16-row fragment
    int akof = (lane >> 4) << 3;          // A: k offset (0 or 8)
    int q8 = lane >> 3;
    int brow = ((q8 & 2) ? 8 : 0) + (lane & 7);   // B: row offset within 16-n pair
    int bkof = (q8 & 1) << 3;                     // B: k offset (0 or 8)
    uint32_t aS = smem_u32(&As[0][0]);
    uint32_t bS = smem_u32(&Bs[0][0]);
    constexpr uint32_t ABUF = BM * LDS * 2;
    constexpr uint32_t BBUF = BN * LDS * 2;

    float acc[MF][NF][4];
    #pragma unroll
    for (int i = 0; i < MF; i++)
        #pragma unroll
        for (int j = 0; j < NF; j++)
            #pragma unroll
            for (int q = 0; q < 4; q++) acc[i][j][q] = 0.f;

    const uint4 zero4 = make_uint4(0, 0, 0, 0);
    int NIT = K / 32;
    uint4 pa[A_LD], pb[B_LD];

    auto load_g = [&](int k0) {
        int k0a = (FOLD && k0 >= FOLD) ? k0 - FOLD : k0;
        #pragma unroll
        for (int q = 0; q < A_LD; q++) {
            int idx = tid + q * 256;
            int row = idx >> 2, seg = idx & 3;
            int gr = m0 + row;
            pa[q] = (gr < M) ? *(const uint4*)(A + (size_t)gr * lda + k0a + seg * 8) : zero4;
        }
        #pragma unroll
        for (int q = 0; q < B_LD; q++) {
            int idx = tid + q * 256;
            if (B_LD * 256 == BN * 4 || idx < BN * 4) {
                int row = idx >> 2, seg = idx & 3;
                pb[q] = *(const uint4*)(B + (size_t)(n0 + row) * K + k0 + seg * 8);
            }
        }
    };
    auto store_s = [&](int buf) {
        #pragma unroll
        for (int q = 0; q < A_LD; q++) {
            int idx = tid + q * 256;
            int row = idx >> 2, seg = idx & 3;
            *(uint4*)&As[buf][row * LDS + seg * 8] = pa[q];
        }
        #pragma unroll
        for (int q = 0; q < B_LD; q++) {
            int idx = tid + q * 256;
            if (B_LD * 256 == BN * 4 || idx < BN * 4) {
                int row = idx >> 2, seg = idx & 3;
                *(uint4*)&Bs[buf][row * LDS + seg * 8] = pb[q];
            }
        }
    };

    load_g(0);
    store_s(0);
    __syncthreads();

    for (int it = 0; it < NIT; it++) {
        int buf = it & 1;
        uint32_t aB = aS + buf * ABUF;
        uint32_t bB = bS + buf * BBUF;
        if (it + 1 < NIT) load_g((it + 1) * 32);
        #pragma unroll
        for (int ks = 0; ks < 32; ks += 16) {
            uint32_t af[MF][4], bf[NF][2];
            #pragma unroll
            for (int mi = 0; mi < MF; mi++)
                ldmatrix_x4(af[mi], aB + 2u * ((wrow + mi * 16 + arow) * LDS + ks + akof));
            #pragma unroll
            for (int nj = 0; nj < NF / 2; nj++) {
                uint32_t tt[4];
                ldmatrix_x4(tt, bB + 2u * ((wcol + nj * 16 + brow) * LDS + ks + bkof));
                bf[2 * nj][0] = tt[0]; bf[2 * nj][1] = tt[1];
                bf[2 * nj + 1][0] = tt[2]; bf[2 * nj + 1][1] = tt[3];
            }
            #pragma unroll
            for (int mi = 0; mi < MF; mi++)
                #pragma unroll
                for (int ni = 0; ni < NF; ni++)
                    mma16816(acc[mi][ni], af[mi], bf[ni]);
        }
        __syncthreads();
        if (it + 1 < NIT) {
            store_s(buf ^ 1);
            __syncthreads();
        }
    }

    // ---- fused attention-coefficient epilogue ----
    if (att_src) {
        float* s1a = (float*)&As[0][0];
        float* s2a = s1a + BM;
        if (tid < BM) { s1a[tid] = 0.f; s2a[tid] = 0.f; }
        __syncthreads();
        float asr[NF][2], adr[NF][2];
        #pragma unroll
        for (int ni = 0; ni < NF; ni++)
            #pragma unroll
            for (int q = 0; q < 2; q++) {
                int gc = n0 + wcol + ni * 8 + 2 * t4 + q;
                asr[ni][q] = att_src[gc];
                adr[ni][q] = att_dst[gc];
            }
        #pragma unroll
        for (int mi = 0; mi < MF; mi++) {
            #pragma unroll
            for (int half = 0; half < 2; half++) {
                float p1 = 0.f, p2 = 0.f;
                #pragma unroll
                for (int ni = 0; ni < NF; ni++)
                    #pragma unroll
                    for (int q = 0; q < 2; q++) {
                        float v = acc[mi][ni][half * 2 + q];
                        p1 += v * asr[ni][q];
                        p2 += v * adr[ni][q];
                    }
                p1 += __shfl_xor_sync(~0u, p1, 1); p1 += __shfl_xor_sync(~0u, p1, 2);
                p2 += __shfl_xor_sync(~0u, p2, 1); p2 += __shfl_xor_sync(~0u, p2, 2);
                if (t4 == 0) {
                    int r = wrow + mi * 16 + half * 8 + g;
                    atomicAdd(&s1a[r], p1);
                    atomicAdd(&s2a[r], p2);
                }
            }
        }
        __syncthreads();
        int head = blockIdx.x % nh;
        if (tid < BM && m0 + tid < M) {
            out_s[(size_t)(m0 + tid) * nh + head] = s1a[tid];
            out_d[(size_t)(m0 + tid) * nh + head] = s2a[tid];
        }
    }

    // ---- C store ----
    #pragma unroll
    for (int mi = 0; mi < MF; mi++) {
        #pragma unroll
        for (int ni = 0; ni < NF; ni++) {
            int r = m0 + wrow + mi * 16 + g;
            int c = n0 + wcol + ni * 8 + 2 * t4;
            if (r < M)     *(float2*)&C[(size_t)r * N + c]       = make_float2(acc[mi][ni][0], acc[mi][ni][1]);
            if (r + 8 < M) *(float2*)&C[(size_t)(r + 8) * N + c] = make_float2(acc[mi][ni][2], acc[mi][ni][3]);
        }
    }
}

// ===== fused layer-1 segment softmax + aggregation + bias + ELU + h1e [hi|lo] =====
__global__ void __launch_bounds__(256) k_smagg1(const float* __restrict__ b1) {
    int d = blockIdx.x;
    int t = threadIdx.x, lane = t & 31, w = t >> 5;
    int jb = g_rowptr[d], je = g_rowptr[d + 1];
    __shared__ float s_m[HEADS], s_rd[HEADS];
    __shared__ int   ssrc[32];
    __shared__ float salpha[32 * HEADS];

    float adst = g_adst1[d * HEADS + w];
    float m = -1e30f;
    for (int j = jb + lane; j < je; j += 32) {
        int s = g_csrsrc[j];
        float v = g_asrc1[s * HEADS + w] + adst;
        v = v > 0.f ? v : 0.2f * v;
        m = fmaxf(m, v);
    }
    #pragma unroll
    for (int o = 16; o; o >>= 1) m = fmaxf(m, __shfl_xor_sync(~0u, m, o));
    float den = 0.f;
    for (int j = jb + lane; j < je; j += 32) {
        int s = g_csrsrc[j];
        float v = g_asrc1[s * HEADS + w] + adst;
        v = v > 0.f ? v : 0.2f * v;
        den += expf(v - m);
    }
    #pragma unroll
    for (int o = 16; o; o >>= 1) den += __shfl_xor_sync(~0u, den, o);
    if (lane == 0) { s_m[w] = m; s_rd[w] = 1.f / (den + 1e-16f); }
    __syncthreads();

    int e8 = t >> 3, h8 = t & 7;
    float m2 = s_m[h8], rd2 = s_rd[h8];
    float adst8 = g_adst1[d * HEADS + h8];
    int h = t >> 5;
    const float4* xl = (const float4*)g_xl1;
    float4 acc = make_float4(0.f, 0.f, 0.f, 0.f);

    for (int j0 = jb; j0 < je; j0 += 32) {
        int cnt = min(32, je - j0);
        __syncthreads();
        if (t < cnt) ssrc[t] = g_csrsrc[j0 + t];
        __syncthreads();
        if (e8 < cnt) {
            int s = ssrc[e8];
            float v = g_asrc1[s * HEADS + h8] + adst8;
            v = v > 0.f ? v : 0.2f * v;
            salpha[e8 * HEADS + h8] = expf(v - m2) * rd2;
        }
        __syncthreads();
        #pragma unroll 2
        for (int jj = 0; jj < cnt; jj++) {
            int s = ssrc[jj];
            float a = salpha[jj * HEADS + h];
            float4 xv = xl[(size_t)s * (F1 / 4) + t];
            acc.x += a * xv.x; acc.y += a * xv.y;
            acc.z += a * xv.z; acc.w += a * xv.w;
        }
    }

    float4 bb = ((const float4*)b1)[t];
    float v[4];
    v[0] = acc.x + bb.x; v[1] = acc.y + bb.y; v[2] = acc.z + bb.z; v[3] = acc.w + bb.w;
    #pragma unroll
    for (int q = 0; q < 4; q++) v[q] = v[q] > 0.f ? v[q] : expm1f(v[q]);
    __nv_bfloat16 hi[4], lo[4];
    #pragma unroll
    for (int q = 0; q < 4; q++) {
        hi[q] = __float2bfloat16(v[q]);
        lo[q] = __float2bfloat16(v[q] - __bfloat162float(hi[q]));
    }
    __nv_bfloat16* row = g_h1e + (size_t)d * K2A;
    *(uint2*)&row[4 * t]      = *(uint2*)hi;
    *(uint2*)&row[4 * t + F1] = *(uint2*)lo;
}

// ===== fused layer-2 segment softmax + aggregation + bias + LayerNorm =====
__global__ void __launch_bounds__(64) k_smagg2ln(
        const float* __restrict__ b2, const float* __restrict__ gamma,
        const float* __restrict__ beta, float* __restrict__ out) {
    int d = blockIdx.x;
    int t = threadIdx.x, lane = t & 31, w = t >> 5;
    int jb = g_rowptr[d], je = g_rowptr[d + 1];
    __shared__ float redm[2], redd[2];
    __shared__ int   ssrc[64];
    __shared__ float salpha[64];

    float adst = g_adst2[d];
    float m = -1e30f;
    for (int j = jb + t; j < je; j += 64) {
        float v = g_asrc2[g_csrsrc[j]] + adst;
        v = v > 0.f ? v : 0.2f * v;
        m = fmaxf(m, v);
    }
    #pragma unroll
    for (int o = 16; o; o >>= 1) m = fmaxf(m, __shfl_xor_sync(~0u, m, o));
    if (lane == 0) redm[w] = m;
    __syncthreads();
    m = fmaxf(redm[0], redm[1]);
    float den = 0.f;
    for (int j = jb + t; j < je; j += 64) {
        float v = g_asrc2[g_csrsrc[j]] + adst;
        v = v > 0.f ? v : 0.2f * v;
        den += expf(v - m);
    }
    #pragma unroll
    for (int o = 16; o; o >>= 1) den += __shfl_xor_sync(~0u, den, o);
    if (lane == 0) redd[w] = den;
    __syncthreads();
    float rd = 1.f / (redd[0] + redd[1] + 1e-16f);

    float acc = 0.f;
    for (int j0 = jb; j0 < je; j0 += 64) {
        int cnt = min(64, je - j0);
        __syncthreads();
        if (t < cnt) {
            int s = g_csrsrc[j0 + t];
            ssrc[t] = s;
            float v = g_asrc2[s] + adst;
            v = v > 0.f ? v : 0.2f * v;
            salpha[t] = expf(v - m) * rd;
        }
        __syncthreads();
        #pragma unroll 2
        for (int jj = 0; jj < cnt; jj++)
            acc += salpha[jj] * g_h2[(size_t)ssrc[jj] * ODIM + t];
    }

    float val = acc + b2[t];
    float s = val;
    #pragma unroll
    for (int o = 16; o; o >>= 1) s += __shfl_xor_sync(~0u, s, o);
    __syncthreads();
    if (lane == 0) redd[w] = s;
    __syncthreads();
    float mu = (redd[0] + redd[1]) * (1.f / 64.f);
    float dv = val - mu;
    float q = dv * dv;
    #pragma unroll
    for (int o = 16; o; o >>= 1) q += __shfl_xor_sync(~0u, q, o);
    __syncthreads();
    if (lane == 0) redm[w] = q;
    __syncthreads();
    float inv = rsqrtf((redm[0] + redm[1]) * (1.f / 64.f) + 1e-5f);
    out[(size_t)d * ODIM + t] = dv * inv * gamma[t] + beta[t];
}

// ================= launch =================
extern "C" void kernel_launch(void* const* d_in, const int* in_sizes, int n_in,
                              void* d_out, int out_size) {
    const float* x     = (const float*)d_in[0];
    const int*   ei    = (const int*)  d_in[1];
    const float* W1    = (const float*)d_in[2];
    const float* as1   = (const float*)d_in[3];
    const float* ad1   = (const float*)d_in[4];
    const float* b1    = (const float*)d_in[5];
    const float* W2    = (const float*)d_in[6];
    const float* as2   = (const float*)d_in[7];
    const float* ad2   = (const float*)d_in[8];
    const float* b2    = (const float*)d_in[9];
    const float* gamma = (const float*)d_in[10];
    const float* beta  = (const float*)d_in[11];
    float* out = (float*)d_out;

    __nv_bfloat16 *xe, *w1e, *h1e, *w2e;
    float *xl1, *h2, *asrc1, *adst1, *asrc2, *adst2;
    cudaGetSymbolAddress((void**)&xe,    g_xe);
    cudaGetSymbolAddress((void**)&w1e,   g_w1e);
    cudaGetSymbolAddress((void**)&h1e,   g_h1e);
    cudaGetSymbolAddress((void**)&w2e,   g_w2e);
    cudaGetSymbolAddress((void**)&xl1,   g_xl1);
    cudaGetSymbolAddress((void**)&h2,    g_h2);
    cudaGetSymbolAddress((void**)&asrc1, g_asrc1);
    cudaGetSymbolAddress((void**)&adst1, g_adst1);
    cudaGetSymbolAddress((void**)&asrc2, g_asrc2);
    cudaGetSymbolAddress((void**)&adst2, g_adst2);

    static cudaStream_t s_side = nullptr;
    static cudaEvent_t  s_ev0 = nullptr, s_ev1 = nullptr;
    if (!s_side) {
        cudaStreamCreateWithFlags(&s_side, cudaStreamNonBlocking);
        cudaEventCreateWithFlags(&s_ev0, cudaEventDisableTiming);
        cudaEventCreateWithFlags(&s_ev1, cudaEventDisableTiming);
    }

    cudaEventRecord(s_ev0, 0);
    cudaStreamWaitEvent(s_side, s_ev0, 0);
    k_csr_init<<<(NN + 255) / 256, 256, 0, s_side>>>();
    k_deg<<<(ET + 255) / 256, 256, 0, s_side>>>(ei);
    k_scan<<<1, 1024, 0, s_side>>>();
    k_scatter<<<(ET + 255) / 256, 256, 0, s_side>>>(ei);
    k_cvt_w2<<<(F1 * ODIM + 255) / 256, 256, 0, s_side>>>(W2);
    cudaEventRecord(s_ev1, s_side);

    k_cvt1<<<(NN * IN_DIM + IN_DIM * F1 + 255) / 256, 256>>>(x, W1);
    {
        dim3 g(F1 / 128, (NN + 127) / 128);
        k_mma_gemm<128, 128, 2, 4, 0><<<g, 256>>>(xe, w1e, xl1, NN, F1, K1E,
                                                  as1, ad1, asrc1, adst1, HEADS);
    }

    cudaStreamWaitEvent(0, s_ev1, 0);

    k_smagg1<<<NN, 256>>>(b1);
    {
        dim3 g(1, (NN + 63) / 64);
        k_mma_gemm<64, 64, 2, 4, F1><<<g, 256>>>(h1e, w2e, h2, NN, ODIM, K2E,
                                                 as2, ad2, asrc2, adst2, 1);
    }
    k_smagg2ln<<<NN, 64>>>(b2, gamma, beta, out);
}

// round 9
// speedup vs baseline: 3.3667x; 1.0941x over previous
#include <cuda_runtime.h>
#include <cuda_bf16.h>
#include <math.h>
#include <stdint.h>

#define NN      10000
#define NE      160000
#define ET      170000
#define IN_DIM  256
#define HID     128
#define HEADS   8
#define F1      1024
#define ODIM    64

#define K1E     (3 * IN_DIM)   // 768  : GEMM1 logical K
#define K1A     (2 * IN_DIM)   // 512  : GEMM1 A physical width [hi|lo]
#define K2E     (3 * F1)       // 3072 : GEMM2 logical K
#define K2A     (2 * F1)       // 2048 : GEMM2 A physical width [hi|lo]
#define SMX     96             // max cached edges per dst in smagg1

// ================= scratch =================
__device__ float g_xl1  [NN * F1];
__device__ float g_asrc1[NN * HEADS];
__device__ float g_adst1[NN * HEADS];
__device__ float g_h2   [NN * ODIM];
__device__ float g_asrc2[NN];
__device__ float g_adst2[NN];
__device__ int g_deg   [NN];
__device__ int g_cursor[NN];
__device__ int g_rowptr[NN + 1];
__device__ int g_csrsrc[ET];
__device__ __nv_bfloat16 g_xe  [NN * K1A];     // [hi | lo]
__device__ __nv_bfloat16 g_w1e [F1 * K1E];     // [hi | lo | hi]
__device__ __nv_bfloat16 g_h1e [NN * K2A];     // [hi | lo]
__device__ __nv_bfloat16 g_w2e [ODIM * K2E];   // [hi | lo | hi]

__device__ __forceinline__ uint32_t smem_u32(const void* p) {
    uint32_t a;
    asm("{ .reg .u64 t; cvta.to.shared.u64 t, %1; cvt.u32.u64 %0, t; }" : "=r"(a) : "l"(p));
    return a;
}
__device__ __forceinline__ void ldmatrix_x4(uint32_t* r, uint32_t addr) {
    asm volatile("ldmatrix.sync.aligned.m8n8.x4.shared.b16 {%0,%1,%2,%3}, [%4];"
        : "=r"(r[0]), "=r"(r[1]), "=r"(r[2]), "=r"(r[3]) : "r"(addr));
}
__device__ __forceinline__ void cp16(uint32_t dst, const void* src, int bytes) {
    asm volatile("cp.async.cg.shared.global [%0], [%1], 16, %2;"
        :: "r"(dst), "l"(src), "r"(bytes));
}
#define CP_COMMIT() asm volatile("cp.async.commit_group;" ::: "memory")
#define CP_WAIT(n)  asm volatile("cp.async.wait_group %0;" :: "n"(n) : "memory")

// ================= CSR build =================
__device__ __forceinline__ void edge_sd(const int* __restrict__ ei, int e, int& s, int& d) {
    if (e < NE) { s = ei[e]; d = ei[NE + e]; }
    else        { s = e - NE; d = e - NE; }
}
__global__ void k_csr_init() {
    int i = blockIdx.x * blockDim.x + threadIdx.x;
    if (i < NN) { g_deg[i] = 0; g_cursor[i] = 0; }
}
__global__ void k_deg(const int* __restrict__ ei) {
    int e = blockIdx.x * blockDim.x + threadIdx.x;
    if (e >= ET) return;
    int d = (e < NE) ? ei[NE + e] : (e - NE);
    atomicAdd(&g_deg[d], 1);
}
__global__ void k_scan() {
    __shared__ int warpsum[32];
    __shared__ int carry_s;
    int t = threadIdx.x, lane = t & 31, w = t >> 5;
    if (t == 0) carry_s = 0;
    __syncthreads();
    for (int base = 0; base < NN; base += 1024) {
        int i = base + t;
        int x = (i < NN) ? g_deg[i] : 0;
        #pragma unroll
        for (int o = 1; o < 32; o <<= 1) {
            int y = __shfl_up_sync(~0u, x, o);
            if (lane >= o) x += y;
        }
        if (lane == 31) warpsum[w] = x;
        __syncthreads();
        if (w == 0) {
            int s = warpsum[lane];
            #pragma unroll
            for (int o = 1; o < 32; o <<= 1) {
                int y = __shfl_up_sync(~0u, s, o);
                if (lane >= o) s += y;
            }
            warpsum[lane] = s;
        }
        __syncthreads();
        int incl = x + (w ? warpsum[w - 1] : 0) + carry_s;
        if (i < NN) g_rowptr[i + 1] = incl;
        __syncthreads();
        if (t == 1023) carry_s = incl;
        __syncthreads();
    }
    if (threadIdx.x == 0) g_rowptr[0] = 0;
}
__global__ void k_scatter(const int* __restrict__ ei) {
    int e = blockIdx.x * blockDim.x + threadIdx.x;
    if (e >= ET) return;
    int s, d; edge_sd(ei, e, s, d);
    int pos = atomicAdd(&g_cursor[d], 1);
    g_csrsrc[g_rowptr[d] + pos] = s;
}

// ================= conversions =================
__global__ void k_cvt1(const float* __restrict__ x, const float* __restrict__ W1) {
    int i = blockIdx.x * blockDim.x + threadIdx.x;
    if (i < NN * IN_DIM) {
        float v = x[i];
        __nv_bfloat16 hi = __float2bfloat16(v);
        __nv_bfloat16 lo = __float2bfloat16(v - __bfloat162float(hi));
        int r = i >> 8, k = i & (IN_DIM - 1);
        __nv_bfloat16* row = g_xe + (size_t)r * K1A;
        row[k] = hi; row[k + IN_DIM] = lo;
        return;
    }
    int j = i - NN * IN_DIM;
    if (j < IN_DIM * F1) {
        int k = j >> 10, n = j & (F1 - 1);
        float v = W1[j];
        __nv_bfloat16 hi = __float2bfloat16(v);
        __nv_bfloat16 lo = __float2bfloat16(v - __bfloat162float(hi));
        __nv_bfloat16* row = g_w1e + (size_t)n * K1E;
        row[k] = hi; row[k + IN_DIM] = lo; row[k + 2 * IN_DIM] = hi;
    }
}
__global__ void k_cvt_w2(const float* __restrict__ W2) {
    int i = blockIdx.x * blockDim.x + threadIdx.x;
    if (i >= F1 * ODIM) return;
    int k = i >> 6, n = i & (ODIM - 1);
    float v = W2[i];
    __nv_bfloat16 hi = __float2bfloat16(v);
    __nv_bfloat16 lo = __float2bfloat16(v - __bfloat162float(hi));
    __nv_bfloat16* row = g_w2e + (size_t)n * K2E;
    row[k] = hi; row[k + F1] = lo; row[k + 2 * F1] = hi;
}

// ================= cp.async-pipelined bf16 mma GEMM =================
// A physical width 2*FOLD ([hi|lo]); logical K = 3*FOLD; k->A col: k>=FOLD ? k-FOLD : k.
__device__ __forceinline__ void mma16816(float* c, const uint32_t* a, const uint32_t* b) {
    asm volatile(
        "mma.sync.aligned.m16n8k16.row.col.f32.bf16.bf16.f32 "
        "{%0,%1,%2,%3}, {%4,%5,%6,%7}, {%8,%9}, {%0,%1,%2,%3};"
        : "+f"(c[0]), "+f"(c[1]), "+f"(c[2]), "+f"(c[3])
        : "r"(a[0]), "r"(a[1]), "r"(a[2]), "r"(a[3]), "r"(b[0]), "r"(b[1]));
}

template<int BM, int BN, int WM, int WN, int FOLD, int STAGES>
__global__ void __launch_bounds__(256) k_mma_gemm(
        const __nv_bfloat16* __restrict__ A,
        const __nv_bfloat16* __restrict__ B,
        float* __restrict__ C, int M, int N, int K,
        const float* __restrict__ att_src, const float* __restrict__ att_dst,
        float* __restrict__ out_s, float* __restrict__ out_d, int nh) {
    constexpr int WT_M = BM / WM;
    constexpr int WT_N = BN / WN;
    constexpr int MF = WT_M / 16;
    constexpr int NF = WT_N / 8;
    constexpr int LDS = 40;
    constexpr int A_LD = BM * 4 / 256;
    constexpr int B_LD = BN * 4 / 256;
    constexpr uint32_t ABUF = BM * LDS * 2;
    constexpr uint32_t BBUF = BN * LDS * 2;

    __shared__ __nv_bfloat16 As[STAGES][BM * LDS];
    __shared__ __nv_bfloat16 Bs[STAGES][BN * LDS];

    int tid = threadIdx.x;
    int w = tid >> 5, lane = tid & 31;
    int g = lane >> 2, t4 = lane & 3;
    int wm = w / WN, wn = w % WN;
    int m0 = blockIdx.y * BM;
    int n0 = blockIdx.x * BN;
    int wrow = wm * WT_M, wcol = wn * WT_N;
    const int lda = 2 * FOLD;
    const int NIT = K / 32;

    int arow = lane & 15;
    int akof = (lane >> 4) << 3;
    int q8 = lane >> 3;
    int brow = ((q8 & 2) ? 8 : 0) + (lane & 7);
    int bkof = (q8 & 1) << 3;
    uint32_t aS = smem_u32(&As[0][0]);
    uint32_t bS = smem_u32(&Bs[0][0]);

    float acc[MF][NF][4];
    #pragma unroll
    for (int i = 0; i < MF; i++)
        #pragma unroll
        for (int j = 0; j < NF; j++)
            #pragma unroll
            for (int q = 0; q < 4; q++) acc[i][j][q] = 0.f;

    auto issue_tile = [&](int it) {
        if (it < NIT) {
            int k0 = it * 32;
            int k0a = (k0 >= FOLD) ? k0 - FOLD : k0;
            int st = it % STAGES;
            #pragma unroll
            for (int q = 0; q < A_LD; q++) {
                int idx = tid + q * 256;
                int row = idx >> 2, seg = idx & 3;
                int gr = m0 + row;
                int grc = gr < M ? gr : M - 1;
                cp16(aS + st * ABUF + 2u * (row * LDS + seg * 8),
                     A + (size_t)grc * lda + k0a + seg * 8, gr < M ? 16 : 0);
            }
            #pragma unroll
            for (int q = 0; q < B_LD; q++) {
                int idx = tid + q * 256;
                if (B_LD * 256 == BN * 4 || idx < BN * 4) {
                    int row = idx >> 2, seg = idx & 3;
                    cp16(bS + st * BBUF + 2u * (row * LDS + seg * 8),
                         B + (size_t)(n0 + row) * K + k0 + seg * 8, 16);
                }
            }
        }
        CP_COMMIT();
    };

    issue_tile(0);
    issue_tile(1);

    for (int it = 0; it < NIT; it++) {
        CP_WAIT(1);
        __syncthreads();
        int st = it % STAGES;
        uint32_t aB = aS + st * ABUF;
        uint32_t bB = bS + st * BBUF;
        #pragma unroll
        for (int ks = 0; ks < 32; ks += 16) {
            uint32_t af[MF][4], bf[NF][2];
            #pragma unroll
            for (int mi = 0; mi < MF; mi++)
                ldmatrix_x4(af[mi], aB + 2u * ((wrow + mi * 16 + arow) * LDS + ks + akof));
            #pragma unroll
            for (int nj = 0; nj < NF / 2; nj++) {
                uint32_t tt[4];
                ldmatrix_x4(tt, bB + 2u * ((wcol + nj * 16 + brow) * LDS + ks + bkof));
                bf[2 * nj][0] = tt[0]; bf[2 * nj][1] = tt[1];
                bf[2 * nj + 1][0] = tt[2]; bf[2 * nj + 1][1] = tt[3];
            }
            #pragma unroll
            for (int mi = 0; mi < MF; mi++)
                #pragma unroll
                for (int ni = 0; ni < NF; ni++)
                    mma16816(acc[mi][ni], af[mi], bf[ni]);
        }
        issue_tile(it + 2);
    }
    CP_WAIT(0);
    __syncthreads();

    // ---- fused attention-coefficient epilogue ----
    if (att_src) {
        float* s1a = (float*)&As[0][0];
        float* s2a = s1a + BM;
        if (tid < BM) { s1a[tid] = 0.f; s2a[tid] = 0.f; }
        __syncthreads();
        float asr[NF][2], adr[NF][2];
        #pragma unroll
        for (int ni = 0; ni < NF; ni++)
            #pragma unroll
            for (int q = 0; q < 2; q++) {
                int gc = n0 + wcol + ni * 8 + 2 * t4 + q;
                asr[ni][q] = att_src[gc];
                adr[ni][q] = att_dst[gc];
            }
        #pragma unroll
        for (int mi = 0; mi < MF; mi++) {
            #pragma unroll
            for (int half = 0; half < 2; half++) {
                float p1 = 0.f, p2 = 0.f;
                #pragma unroll
                for (int ni = 0; ni < NF; ni++)
                    #pragma unroll
                    for (int q = 0; q < 2; q++) {
                        float v = acc[mi][ni][half * 2 + q];
                        p1 += v * asr[ni][q];
                        p2 += v * adr[ni][q];
                    }
                p1 += __shfl_xor_sync(~0u, p1, 1); p1 += __shfl_xor_sync(~0u, p1, 2);
                p2 += __shfl_xor_sync(~0u, p2, 1); p2 += __shfl_xor_sync(~0u, p2, 2);
                if (t4 == 0) {
                    int r = wrow + mi * 16 + half * 8 + g;
                    atomicAdd(&s1a[r], p1);
                    atomicAdd(&s2a[r], p2);
                }
            }
        }
        __syncthreads();
        int head = blockIdx.x % nh;
        if (tid < BM && m0 + tid < M) {
            out_s[(size_t)(m0 + tid) * nh + head] = s1a[tid];
            out_d[(size_t)(m0 + tid) * nh + head] = s2a[tid];
        }
    }

    // ---- C store ----
    #pragma unroll
    for (int mi = 0; mi < MF; mi++) {
        #pragma unroll
        for (int ni = 0; ni < NF; ni++) {
            int r = m0 + wrow + mi * 16 + g;
            int c = n0 + wcol + ni * 8 + 2 * t4;
            if (r < M)     *(float2*)&C[(size_t)r * N + c]       = make_float2(acc[mi][ni][0], acc[mi][ni][1]);
            if (r + 8 < M) *(float2*)&C[(size_t)(r + 8) * N + c] = make_float2(acc[mi][ni][2], acc[mi][ni][3]);
        }
    }
}

// ===== fused layer-1 softmax + aggregation + bias + ELU, exp cached in smem =====
__global__ void __launch_bounds__(256) k_smagg1(const float* __restrict__ b1) {
    int d = blockIdx.x;
    int t = threadIdx.x, lane = t & 31, w = t >> 5;
    int jb = g_rowptr[d], je = g_rowptr[d + 1];
    __shared__ float s_m[HEADS], s_rd[HEADS];
    __shared__ float sv[SMX * HEADS];
    __shared__ int   ssrc[32];
    __shared__ float salpha[32 * HEADS];

    float adst = g_adst1[d * HEADS + w];
    float m = -1e30f;
    for (int j = jb + lane; j < je; j += 32) {
        int s = g_csrsrc[j];
        float v = g_asrc1[s * HEADS + w] + adst;
        v = v > 0.f ? v : 0.2f * v;
        int idx = j - jb;
        if (idx < SMX) sv[idx * HEADS + w] = v;
        m = fmaxf(m, v);
    }
    #pragma unroll
    for (int o = 16; o; o >>= 1) m = fmaxf(m, __shfl_xor_sync(~0u, m, o));
    float den = 0.f;
    for (int j = jb + lane; j < je; j += 32) {
        int idx = j - jb;
        float v;
        if (idx < SMX) v = sv[idx * HEADS + w];
        else {
            v = g_asrc1[g_csrsrc[j] * HEADS + w] + adst;
            v = v > 0.f ? v : 0.2f * v;
        }
        float e = expf(v - m);
        if (idx < SMX) sv[idx * HEADS + w] = e;
        den += e;
    }
    #pragma unroll
    for (int o = 16; o; o >>= 1) den += __shfl_xor_sync(~0u, den, o);
    if (lane == 0) { s_m[w] = m; s_rd[w] = 1.f / (den + 1e-16f); }
    __syncthreads();

    int e8 = t >> 3, h8 = t & 7;
    float rd2 = s_rd[h8], m2 = s_m[h8];
    float adst8 = g_adst1[d * HEADS + h8];
    int h = t >> 5;
    const float4* xl = (const float4*)g_xl1;
    float4 acc = make_float4(0.f, 0.f, 0.f, 0.f);

    for (int j0 = jb; j0 < je; j0 += 32) {
        int cnt = min(32, je - j0);
        __syncthreads();
        if (t < cnt) ssrc[t] = g_csrsrc[j0 + t];
        __syncthreads();
        if (e8 < cnt) {
            int idx = j0 - jb + e8;
            float e;
            if (idx < SMX) e = sv[idx * HEADS + h8];
            else {
                float v = g_asrc1[ssrc[e8] * HEADS + h8] + adst8;
                v = v > 0.f ? v : 0.2f * v;
                e = expf(v - m2);
            }
            salpha[e8 * HEADS + h8] = e * rd2;
        }
        __syncthreads();
        #pragma unroll 2
        for (int jj = 0; jj < cnt; jj++) {
            int s = ssrc[jj];
            float a = salpha[jj * HEADS + h];
            float4 xv = xl[(size_t)s * (F1 / 4) + t];
            acc.x += a * xv.x; acc.y += a * xv.y;
            acc.z += a * xv.z; acc.w += a * xv.w;
        }
    }

    float4 bb = ((const float4*)b1)[t];
    float v[4];
    v[0] = acc.x + bb.x; v[1] = acc.y + bb.y; v[2] = acc.z + bb.z; v[3] = acc.w + bb.w;
    #pragma unroll
    for (int q = 0; q < 4; q++) v[q] = v[q] > 0.f ? v[q] : expm1f(v[q]);
    __nv_bfloat16 hi[4], lo[4];
    #pragma unroll
    for (int q = 0; q < 4; q++) {
        hi[q] = __float2bfloat16(v[q]);
        lo[q] = __float2bfloat16(v[q] - __bfloat162float(hi[q]));
    }
    __nv_bfloat16* row = g_h1e + (size_t)d * K2A;
    *(uint2*)&row[4 * t]      = *(uint2*)hi;
    *(uint2*)&row[4 * t + F1] = *(uint2*)lo;
}

// ===== fused layer-2 softmax + aggregation + bias + LayerNorm =====
__global__ void __launch_bounds__(64) k_smagg2ln(
        const float* __restrict__ b2, const float* __restrict__ gamma,
        const float* __restrict__ beta, float* __restrict__ out) {
    int d = blockIdx.x;
    int t = threadIdx.x, lane = t & 31, w = t >> 5;
    int jb = g_rowptr[d], je = g_rowptr[d + 1];
    __shared__ float redm[2], redd[2];
    __shared__ int   ssrc[64];
    __shared__ float salpha[64];

    float adst = g_adst2[d];
    float m = -1e30f;
    for (int j = jb + t; j < je; j += 64) {
        float v = g_asrc2[g_csrsrc[j]] + adst;
        v = v > 0.f ? v : 0.2f * v;
        m = fmaxf(m, v);
    }
    #pragma unroll
    for (int o = 16; o; o >>= 1) m = fmaxf(m, __shfl_xor_sync(~0u, m, o));
    if (lane == 0) redm[w] = m;
    __syncthreads();
    m = fmaxf(redm[0], redm[1]);
    float den = 0.f;
    for (int j = jb + t; j < je; j += 64) {
        float v = g_asrc2[g_csrsrc[j]] + adst;
        v = v > 0.f ? v : 0.2f * v;
        den += expf(v - m);
    }
    #pragma unroll
    for (int o = 16; o; o >>= 1) den += __shfl_xor_sync(~0u, den, o);
    if (lane == 0) redd[w] = den;
    __syncthreads();
    float rd = 1.f / (redd[0] + redd[1] + 1e-16f);

    float acc = 0.f;
    for (int j0 = jb; j0 < je; j0 += 64) {
        int cnt = min(64, je - j0);
        __syncthreads();
        if (t < cnt) {
            int s = g_csrsrc[j0 + t];
            ssrc[t] = s;
            float v = g_asrc2[s] + adst;
            v = v > 0.f ? v : 0.2f * v;
            salpha[t] = expf(v - m) * rd;
        }
        __syncthreads();
        #pragma unroll 2
        for (int jj = 0; jj < cnt; jj++)
            acc += salpha[jj] * g_h2[(size_t)ssrc[jj] * ODIM + t];
    }

    float val = acc + b2[t];
    float s = val;
    #pragma unroll
    for (int o = 16; o; o >>= 1) s += __shfl_xor_sync(~0u, s, o);
    __syncthreads();
    if (lane == 0) redd[w] = s;
    __syncthreads();
    float mu = (redd[0] + redd[1]) * (1.f / 64.f);
    float dv = val - mu;
    float q = dv * dv;
    #pragma unroll
    for (int o = 16; o; o >>= 1) q += __shfl_xor_sync(~0u, q, o);
    __syncthreads();
    if (lane == 0) redm[w] = q;
    __syncthreads();
    float inv = rsqrtf((redm[0] + redm[1]) * (1.f / 64.f) + 1e-5f);
    out[(size_t)d * ODIM + t] = dv * inv * gamma[t] + beta[t];
}

// ================= launch =================
extern "C" void kernel_launch(void* const* d_in, const int* in_sizes, int n_in,
                              void* d_out, int out_size) {
    const float* x     = (const float*)d_in[0];
    const int*   ei    = (const int*)  d_in[1];
    const float* W1    = (const float*)d_in[2];
    const float* as1   = (const float*)d_in[3];
    const float* ad1   = (const float*)d_in[4];
    const float* b1    = (const float*)d_in[5];
    const float* W2    = (const float*)d_in[6];
    const float* as2   = (const float*)d_in[7];
    const float* ad2   = (const float*)d_in[8];
    const float* b2    = (const float*)d_in[9];
    const float* gamma = (const float*)d_in[10];
    const float* beta  = (const float*)d_in[11];
    float* out = (float*)d_out;

    __nv_bfloat16 *xe, *w1e, *h1e, *w2e;
    float *xl1, *h2, *asrc1, *adst1, *asrc2, *adst2;
    cudaGetSymbolAddress((void**)&xe,    g_xe);
    cudaGetSymbolAddress((void**)&w1e,   g_w1e);
    cudaGetSymbolAddress((void**)&h1e,   g_h1e);
    cudaGetSymbolAddress((void**)&w2e,   g_w2e);
    cudaGetSymbolAddress((void**)&xl1,   g_xl1);
    cudaGetSymbolAddress((void**)&h2,    g_h2);
    cudaGetSymbolAddress((void**)&asrc1, g_asrc1);
    cudaGetSymbolAddress((void**)&adst1, g_adst1);
    cudaGetSymbolAddress((void**)&asrc2, g_asrc2);
    cudaGetSymbolAddress((void**)&adst2, g_adst2);

    static cudaStream_t s_side = nullptr;
    static cudaEvent_t  s_ev0 = nullptr, s_ev1 = nullptr;
    if (!s_side) {
        cudaStreamCreateWithFlags(&s_side, cudaStreamNonBlocking);
        cudaEventCreateWithFlags(&s_ev0, cudaEventDisableTiming);
        cudaEventCreateWithFlags(&s_ev1, cudaEventDisableTiming);
    }

    cudaEventRecord(s_ev0, 0);
    cudaStreamWaitEvent(s_side, s_ev0, 0);

    // submission order chosen so GEMM1 is the 4th kernel (profiler visibility)
    k_cvt1<<<(NN * IN_DIM + IN_DIM * F1 + 255) / 256, 256>>>(x, W1);       // 0
    k_csr_init<<<(NN + 255) / 256, 256, 0, s_side>>>();                     // 1
    k_deg<<<(ET + 255) / 256, 256, 0, s_side>>>(ei);                        // 2
    {
        dim3 g(F1 / 128, (NN + 127) / 128);
        k_mma_gemm<128, 128, 2, 4, IN_DIM, 3><<<g, 256>>>(                  // 3
            xe, w1e, xl1, NN, F1, K1E, as1, ad1, asrc1, adst1, HEADS);
    }
    k_scan<<<1, 1024, 0, s_side>>>();                                       // 4
    k_scatter<<<(ET + 255) / 256, 256, 0, s_side>>>(ei);                    // 5
    k_cvt_w2<<<(F1 * ODIM + 255) / 256, 256, 0, s_side>>>(W2);              // 6
    cudaEventRecord(s_ev1, s_side);
    cudaStreamWaitEvent(0, s_ev1, 0);

    k_smagg1<<<NN, 256>>>(b1);                                              // 7
    {
        dim3 g(1, (NN + 63) / 64);
        k_mma_gemm<64, 64, 2, 4, F1, 4><<<g, 256>>>(                        // 8
            h1e, w2e, h2, NN, ODIM, K2E, as2, ad2, asrc2, adst2, 1);
    }
    k_smagg2ln<<<NN, 64>>>(b2, gamma, beta, out);                           // 9
}

// round 10
// speedup vs baseline: 3.4944x; 1.0379x over previous
#include <cuda_runtime.h>
#include <cuda_bf16.h>
#include <math.h>
#include <stdint.h>

#define NN      10000
#define NE      160000
#define ET      170000
#define IN_DIM  256
#define HID     128
#define HEADS   8
#define F1      1024
#define ODIM    64

#define K1E     (3 * IN_DIM)   // 768  : GEMM1 logical K
#define K1A     (2 * IN_DIM)   // 512  : GEMM1 A physical width [hi|lo]
#define K2E     (3 * F1)       // 3072 : GEMM2 logical K
#define K2A     (2 * F1)       // 2048 : GEMM2 A physical width [hi|lo]
#define SMX     96             // max cached edges per dst in smagg1

// ================= scratch =================
__device__ float g_xl1  [NN * F1];
__device__ float g_asrc1[NN * HEADS];
__device__ float g_adst1[NN * HEADS];
__device__ float g_h2   [NN * ODIM];
__device__ float g_asrc2[NN];
__device__ float g_adst2[NN];
__device__ int g_deg   [NN];
__device__ int g_cursor[NN];
__device__ int g_rowptr[NN + 1];
__device__ int g_csrsrc[ET];
__device__ __nv_bfloat16 g_xe  [NN * K1A];     // [hi | lo]
__device__ __nv_bfloat16 g_w1e [F1 * K1E];     // [hi | lo | hi]
__device__ __nv_bfloat16 g_h1e [NN * K2A];     // [hi | lo]
__device__ __nv_bfloat16 g_w2e [ODIM * K2E];   // [hi | lo | hi]

__device__ __forceinline__ uint32_t smem_u32(const void* p) {
    uint32_t a;
    asm("{ .reg .u64 t; cvta.to.shared.u64 t, %1; cvt.u32.u64 %0, t; }" : "=r"(a) : "l"(p));
    return a;
}
__device__ __forceinline__ void ldmatrix_x4(uint32_t* r, uint32_t addr) {
    asm volatile("ldmatrix.sync.aligned.m8n8.x4.shared.b16 {%0,%1,%2,%3}, [%4];"
        : "=r"(r[0]), "=r"(r[1]), "=r"(r[2]), "=r"(r[3]) : "r"(addr));
}
__device__ __forceinline__ void cp16(uint32_t dst, const void* src, int bytes) {
    asm volatile("cp.async.cg.shared.global [%0], [%1], 16, %2;"
        :: "r"(dst), "l"(src), "r"(bytes));
}
#define CP_COMMIT() asm volatile("cp.async.commit_group;" ::: "memory")
#define CP_WAIT(n)  asm volatile("cp.async.wait_group %0;" :: "n"(n) : "memory")

// ================= CSR build =================
__device__ __forceinline__ void edge_sd(const int* __restrict__ ei, int e, int& s, int& d) {
    if (e < NE) { s = ei[e]; d = ei[NE + e]; }
    else        { s = e - NE; d = e - NE; }
}
__global__ void k_csr_init() {
    int i = blockIdx.x * blockDim.x + threadIdx.x;
    if (i < NN) { g_deg[i] = 0; g_cursor[i] = 0; }
}
__global__ void k_deg(const int* __restrict__ ei) {
    int e = blockIdx.x * blockDim.x + threadIdx.x;
    if (e >= ET) return;
    int d = (e < NE) ? ei[NE + e] : (e - NE);
    atomicAdd(&g_deg[d], 1);
}
__global__ void k_scan() {
    __shared__ int warpsum[32];
    __shared__ int carry_s;
    int t = threadIdx.x, lane = t & 31, w = t >> 5;
    if (t == 0) carry_s = 0;
    __syncthreads();
    for (int base = 0; base < NN; base += 1024) {
        int i = base + t;
        int x = (i < NN) ? g_deg[i] : 0;
        #pragma unroll
        for (int o = 1; o < 32; o <<= 1) {
            int y = __shfl_up_sync(~0u, x, o);
            if (lane >= o) x += y;
        }
        if (lane == 31) warpsum[w] = x;
        __syncthreads();
        if (w == 0) {
            int s = warpsum[lane];
            #pragma unroll
            for (int o = 1; o < 32; o <<= 1) {
                int y = __shfl_up_sync(~0u, s, o);
                if (lane >= o) s += y;
            }
            warpsum[lane] = s;
        }
        __syncthreads();
        int incl = x + (w ? warpsum[w - 1] : 0) + carry_s;
        if (i < NN) g_rowptr[i + 1] = incl;
        __syncthreads();
        if (t == 1023) carry_s = incl;
        __syncthreads();
    }
    if (threadIdx.x == 0) g_rowptr[0] = 0;
}
__global__ void k_scatter(const int* __restrict__ ei) {
    int e = blockIdx.x * blockDim.x + threadIdx.x;
    if (e >= ET) return;
    int s, d; edge_sd(ei, e, s, d);
    int pos = atomicAdd(&g_cursor[d], 1);
    g_csrsrc[g_rowptr[d] + pos] = s;
}

// ================= conversions =================
__global__ void k_cvt1(const float* __restrict__ x, const float* __restrict__ W1) {
    int i = blockIdx.x * blockDim.x + threadIdx.x;
    if (i < NN * IN_DIM) {
        float v = x[i];
        __nv_bfloat16 hi = __float2bfloat16(v);
        __nv_bfloat16 lo = __float2bfloat16(v - __bfloat162float(hi));
        int r = i >> 8, k = i & (IN_DIM - 1);
        __nv_bfloat16* row = g_xe + (size_t)r * K1A;
        row[k] = hi; row[k + IN_DIM] = lo;
        return;
    }
    int j = i - NN * IN_DIM;
    if (j < IN_DIM * F1) {
        int k = j >> 10, n = j & (F1 - 1);
        float v = W1[j];
        __nv_bfloat16 hi = __float2bfloat16(v);
        __nv_bfloat16 lo = __float2bfloat16(v - __bfloat162float(hi));
        __nv_bfloat16* row = g_w1e + (size_t)n * K1E;
        row[k] = hi; row[k + IN_DIM] = lo; row[k + 2 * IN_DIM] = hi;
    }
}
__global__ void k_cvt_w2(const float* __restrict__ W2) {
    int i = blockIdx.x * blockDim.x + threadIdx.x;
    if (i >= F1 * ODIM) return;
    int k = i >> 6, n = i & (ODIM - 1);
    float v = W2[i];
    __nv_bfloat16 hi = __float2bfloat16(v);
    __nv_bfloat16 lo = __float2bfloat16(v - __bfloat162float(hi));
    __nv_bfloat16* row = g_w2e + (size_t)n * K2E;
    row[k] = hi; row[k + F1] = lo; row[k + 2 * F1] = hi;
}

// ================= cp.async-pipelined bf16 mma GEMM (n_off = column offset) =====
__device__ __forceinline__ void mma16816(float* c, const uint32_t* a, const uint32_t* b) {
    asm volatile(
        "mma.sync.aligned.m16n8k16.row.col.f32.bf16.bf16.f32 "
        "{%0,%1,%2,%3}, {%4,%5,%6,%7}, {%8,%9}, {%0,%1,%2,%3};"
        : "+f"(c[0]), "+f"(c[1]), "+f"(c[2]), "+f"(c[3])
        : "r"(a[0]), "r"(a[1]), "r"(a[2]), "r"(a[3]), "r"(b[0]), "r"(b[1]));
}

template<int BM, int BN, int WM, int WN, int FOLD, int STAGES>
__global__ void __launch_bounds__(256) k_mma_gemm(
        const __nv_bfloat16* __restrict__ A,
        const __nv_bfloat16* __restrict__ B,
        float* __restrict__ C, int M, int N, int K, int n_off,
        const float* __restrict__ att_src, const float* __restrict__ att_dst,
        float* __restrict__ out_s, float* __restrict__ out_d, int nh) {
    constexpr int WT_M = BM / WM;
    constexpr int WT_N = BN / WN;
    constexpr int MF = WT_M / 16;
    constexpr int NF = WT_N / 8;
    constexpr int LDS = 40;
    constexpr int A_LD = BM * 4 / 256;
    constexpr int B_LD = BN * 4 / 256;
    constexpr uint32_t ABUF = BM * LDS * 2;
    constexpr uint32_t BBUF = BN * LDS * 2;

    __shared__ __nv_bfloat16 As[STAGES][BM * LDS];
    __shared__ __nv_bfloat16 Bs[STAGES][BN * LDS];

    int tid = threadIdx.x;
    int w = tid >> 5, lane = tid & 31;
    int g = lane >> 2, t4 = lane & 3;
    int wm = w / WN, wn = w % WN;
    int m0 = blockIdx.y * BM;
    int n0 = blockIdx.x * BN + n_off;
    int wrow = wm * WT_M, wcol = wn * WT_N;
    const int lda = 2 * FOLD;
    const int NIT = K / 32;

    int arow = lane & 15;
    int akof = (lane >> 4) << 3;
    int q8 = lane >> 3;
    int brow = ((q8 & 2) ? 8 : 0) + (lane & 7);
    int bkof = (q8 & 1) << 3;
    uint32_t aS = smem_u32(&As[0][0]);
    uint32_t bS = smem_u32(&Bs[0][0]);

    float acc[MF][NF][4];
    #pragma unroll
    for (int i = 0; i < MF; i++)
        #pragma unroll
        for (int j = 0; j < NF; j++)
            #pragma unroll
            for (int q = 0; q < 4; q++) acc[i][j][q] = 0.f;

    auto issue_tile = [&](int it) {
        if (it < NIT) {
            int k0 = it * 32;
            int k0a = (k0 >= FOLD) ? k0 - FOLD : k0;
            int st = it % STAGES;
            #pragma unroll
            for (int q = 0; q < A_LD; q++) {
                int idx = tid + q * 256;
                int row = idx >> 2, seg = idx & 3;
                int gr = m0 + row;
                int grc = gr < M ? gr : M - 1;
                cp16(aS + st * ABUF + 2u * (row * LDS + seg * 8),
                     A + (size_t)grc * lda + k0a + seg * 8, gr < M ? 16 : 0);
            }
            #pragma unroll
            for (int q = 0; q < B_LD; q++) {
                int idx = tid + q * 256;
                if (B_LD * 256 == BN * 4 || idx < BN * 4) {
                    int row = idx >> 2, seg = idx & 3;
                    cp16(bS + st * BBUF + 2u * (row * LDS + seg * 8),
                         B + (size_t)(n0 + row) * K + k0 + seg * 8, 16);
                }
            }
        }
        CP_COMMIT();
    };

    issue_tile(0);
    issue_tile(1);

    for (int it = 0; it < NIT; it++) {
        CP_WAIT(1);
        __syncthreads();
        int st = it % STAGES;
        uint32_t aB = aS + st * ABUF;
        uint32_t bB = bS + st * BBUF;
        #pragma unroll
        for (int ks = 0; ks < 32; ks += 16) {
            uint32_t af[MF][4], bf[NF][2];
            #pragma unroll
            for (int mi = 0; mi < MF; mi++)
                ldmatrix_x4(af[mi], aB + 2u * ((wrow + mi * 16 + arow) * LDS + ks + akof));
            #pragma unroll
            for (int nj = 0; nj < NF / 2; nj++) {
                uint32_t tt[4];
                ldmatrix_x4(tt, bB + 2u * ((wcol + nj * 16 + brow) * LDS + ks + bkof));
                bf[2 * nj][0] = tt[0]; bf[2 * nj][1] = tt[1];
                bf[2 * nj + 1][0] = tt[2]; bf[2 * nj + 1][1] = tt[3];
            }
            #pragma unroll
            for (int mi = 0; mi < MF; mi++)
                #pragma unroll
                for (int ni = 0; ni < NF; ni++)
                    mma16816(acc[mi][ni], af[mi], bf[ni]);
        }
        issue_tile(it + 2);
    }
    CP_WAIT(0);
    __syncthreads();

    // ---- fused attention-coefficient epilogue ----
    if (att_src) {
        float* s1a = (float*)&As[0][0];
        float* s2a = s1a + BM;
        if (tid < BM) { s1a[tid] = 0.f; s2a[tid] = 0.f; }
        __syncthreads();
        float asr[NF][2], adr[NF][2];
        #pragma unroll
        for (int ni = 0; ni < NF; ni++)
            #pragma unroll
            for (int q = 0; q < 2; q++) {
                int gc = n0 + wcol + ni * 8 + 2 * t4 + q;
                asr[ni][q] = att_src[gc];
                adr[ni][q] = att_dst[gc];
            }
        #pragma unroll
        for (int mi = 0; mi < MF; mi++) {
            #pragma unroll
            for (int half = 0; half < 2; half++) {
                float p1 = 0.f, p2 = 0.f;
                #pragma unroll
                for (int ni = 0; ni < NF; ni++)
                    #pragma unroll
                    for (int q = 0; q < 2; q++) {
                        float v = acc[mi][ni][half * 2 + q];
                        p1 += v * asr[ni][q];
                        p2 += v * adr[ni][q];
                    }
                p1 += __shfl_xor_sync(~0u, p1, 1); p1 += __shfl_xor_sync(~0u, p1, 2);
                p2 += __shfl_xor_sync(~0u, p2, 1); p2 += __shfl_xor_sync(~0u, p2, 2);
                if (t4 == 0) {
                    int r = wrow + mi * 16 + half * 8 + g;
                    atomicAdd(&s1a[r], p1);
                    atomicAdd(&s2a[r], p2);
                }
            }
        }
        __syncthreads();
        int head = (n0 / BN) % nh;
        if (tid < BM && m0 + tid < M) {
            out_s[(size_t)(m0 + tid) * nh + head] = s1a[tid];
            out_d[(size_t)(m0 + tid) * nh + head] = s2a[tid];
        }
    }

    // ---- C store ----
    #pragma unroll
    for (int mi = 0; mi < MF; mi++) {
        #pragma unroll
        for (int ni = 0; ni < NF; ni++) {
            int r = m0 + wrow + mi * 16 + g;
            int c = n0 + wcol + ni * 8 + 2 * t4;
            if (r < M)     *(float2*)&C[(size_t)r * N + c]       = make_float2(acc[mi][ni][0], acc[mi][ni][1]);
            if (r + 8 < M) *(float2*)&C[(size_t)(r + 8) * N + c] = make_float2(acc[mi][ni][2], acc[mi][ni][3]);
        }
    }
}

// ===== fused layer-1 softmax + agg + bias + ELU for 4 heads [h0, h0+4) =====
// block per dst, 128 threads = 4 warps (warp = head in phase 1).
__global__ void __launch_bounds__(128) k_smagg1(const float* __restrict__ b1, int h0) {
    int d = blockIdx.x;
    int t = threadIdx.x, lane = t & 31, w = t >> 5;
    int jb = g_rowptr[d], je = g_rowptr[d + 1];
    __shared__ float s_m[4], s_rd[4];
    __shared__ float sv[SMX * 4];
    __shared__ int   ssrc[32];
    __shared__ float salpha[32 * 4];

    int gh = h0 + w;                       // phase-1 head for this warp
    float adst = g_adst1[d * HEADS + gh];
    float m = -1e30f;
    for (int j = jb + lane; j < je; j += 32) {
        int s = g_csrsrc[j];
        float v = g_asrc1[s * HEADS + gh] + adst;
        v = v > 0.f ? v : 0.2f * v;
        int idx = j - jb;
        if (idx < SMX) sv[idx * 4 + w] = v;
        m = fmaxf(m, v);
    }
    #pragma unroll
    for (int o = 16; o; o >>= 1) m = fmaxf(m, __shfl_xor_sync(~0u, m, o));
    float den = 0.f;
    for (int j = jb + lane; j < je; j += 32) {
        int idx = j - jb;
        float v;
        if (idx < SMX) v = sv[idx * 4 + w];
        else {
            v = g_asrc1[g_csrsrc[j] * HEADS + gh] + adst;
            v = v > 0.f ? v : 0.2f * v;
        }
        float e = expf(v - m);
        if (idx < SMX) sv[idx * 4 + w] = e;
        den += e;
    }
    #pragma unroll
    for (int o = 16; o; o >>= 1) den += __shfl_xor_sync(~0u, den, o);
    if (lane == 0) { s_m[w] = m; s_rd[w] = 1.f / (den + 1e-16f); }
    __syncthreads();

    int e4 = t >> 2, h4 = t & 3;          // alpha mapping: 32 edges x 4 heads
    float rd2 = s_rd[h4], m2 = s_m[h4];
    float adst4 = g_adst1[d * HEADS + h0 + h4];
    int lh = t >> 5;                       // channel-group local head
    int fc = h0 * 32 + t;                  // global float4 column
    const float4* xl = (const float4*)g_xl1;
    float4 acc = make_float4(0.f, 0.f, 0.f, 0.f);

    for (int j0 = jb; j0 < je; j0 += 32) {
        int cnt = min(32, je - j0);
        __syncthreads();
        if (t < cnt) ssrc[t] = g_csrsrc[j0 + t];
        __syncthreads();
        if (e4 < cnt) {
            int idx = j0 - jb + e4;
            float e;
            if (idx < SMX) e = sv[idx * 4 + h4];
            else {
                float v = g_asrc1[ssrc[e4] * HEADS + h0 + h4] + adst4;
                v = v > 0.f ? v : 0.2f * v;
                e = expf(v - m2);
            }
            salpha[e4 * 4 + h4] = e * rd2;
        }
        __syncthreads();
        #pragma unroll 2
        for (int jj = 0; jj < cnt; jj++) {
            int s = ssrc[jj];
            float a = salpha[jj * 4 + lh];
            float4 xv = xl[(size_t)s * (F1 / 4) + fc];
            acc.x += a * xv.x; acc.y += a * xv.y;
            acc.z += a * xv.z; acc.w += a * xv.w;
        }
    }

    float4 bb = ((const float4*)b1)[fc];
    float v[4];
    v[0] = acc.x + bb.x; v[1] = acc.y + bb.y; v[2] = acc.z + bb.z; v[3] = acc.w + bb.w;
    #pragma unroll
    for (int q = 0; q < 4; q++) v[q] = v[q] > 0.f ? v[q] : expm1f(v[q]);
    __nv_bfloat16 hi[4], lo[4];
    #pragma unroll
    for (int q = 0; q < 4; q++) {
        hi[q] = __float2bfloat16(v[q]);
        lo[q] = __float2bfloat16(v[q] - __bfloat162float(hi[q]));
    }
    __nv_bfloat16* row = g_h1e + (size_t)d * K2A;
    *(uint2*)&row[4 * fc]      = *(uint2*)hi;
    *(uint2*)&row[4 * fc + F1] = *(uint2*)lo;
}

// ===== fused layer-2 softmax + aggregation + bias + LayerNorm =====
__global__ void __launch_bounds__(64) k_smagg2ln(
        const float* __restrict__ b2, const float* __restrict__ gamma,
        const float* __restrict__ beta, float* __restrict__ out) {
    int d = blockIdx.x;
    int t = threadIdx.x, lane = t & 31, w = t >> 5;
    int jb = g_rowptr[d], je = g_rowptr[d + 1];
    __shared__ float redm[2], redd[2];
    __shared__ int   ssrc[64];
    __shared__ float salpha[64];

    float adst = g_adst2[d];
    float m = -1e30f;
    for (int j = jb + t; j < je; j += 64) {
        float v = g_asrc2[g_csrsrc[j]] + adst;
        v = v > 0.f ? v : 0.2f * v;
        m = fmaxf(m, v);
    }
    #pragma unroll
    for (int o = 16; o; o >>= 1) m = fmaxf(m, __shfl_xor_sync(~0u, m, o));
    if (lane == 0) redm[w] = m;
    __syncthreads();
    m = fmaxf(redm[0], redm[1]);
    float den = 0.f;
    for (int j = jb + t; j < je; j += 64) {
        float v = g_asrc2[g_csrsrc[j]] + adst;
        v = v > 0.f ? v : 0.2f * v;
        den += expf(v - m);
    }
    #pragma unroll
    for (int o = 16; o; o >>= 1) den += __shfl_xor_sync(~0u, den, o);
    if (lane == 0) redd[w] = den;
    __syncthreads();
    float rd = 1.f / (redd[0] + redd[1] + 1e-16f);

    float acc = 0.f;
    for (int j0 = jb; j0 < je; j0 += 64) {
        int cnt = min(64, je - j0);
        __syncthreads();
        if (t < cnt) {
            int s = g_csrsrc[j0 + t];
            ssrc[t] = s;
            float v = g_asrc2[s] + adst;
            v = v > 0.f ? v : 0.2f * v;
            salpha[t] = expf(v - m) * rd;
        }
        __syncthreads();
        #pragma unroll 2
        for (int jj = 0; jj < cnt; jj++)
            acc += salpha[jj] * g_h2[(size_t)ssrc[jj] * ODIM + t];
    }

    float val = acc + b2[t];
    float s = val;
    #pragma unroll
    for (int o = 16; o; o >>= 1) s += __shfl_xor_sync(~0u, s, o);
    __syncthreads();
    if (lane == 0) redd[w] = s;
    __syncthreads();
    float mu = (redd[0] + redd[1]) * (1.f / 64.f);
    float dv = val - mu;
    float q = dv * dv;
    #pragma unroll
    for (int o = 16; o; o >>= 1) q += __shfl_xor_sync(~0u, q, o);
    __syncthreads();
    if (lane == 0) redm[w] = q;
    __syncthreads();
    float inv = rsqrtf((redm[0] + redm[1]) * (1.f / 64.f) + 1e-5f);
    out[(size_t)d * ODIM + t] = dv * inv * gamma[t] + beta[t];
}

// ================= launch =================
extern "C" void kernel_launch(void* const* d_in, const int* in_sizes, int n_in,
                              void* d_out, int out_size) {
    const float* x     = (const float*)d_in[0];
    const int*   ei    = (const int*)  d_in[1];
    const float* W1    = (const float*)d_in[2];
    const float* as1   = (const float*)d_in[3];
    const float* ad1   = (const float*)d_in[4];
    const float* b1    = (const float*)d_in[5];
    const float* W2    = (const float*)d_in[6];
    const float* as2   = (const float*)d_in[7];
    const float* ad2   = (const float*)d_in[8];
    const float* b2    = (const float*)d_in[9];
    const float* gamma = (const float*)d_in[10];
    const float* beta  = (const float*)d_in[11];
    float* out = (float*)d_out;

    __nv_bfloat16 *xe, *w1e, *h1e, *w2e;
    float *xl1, *h2, *asrc1, *adst1, *asrc2, *adst2;
    cudaGetSymbolAddress((void**)&xe,    g_xe);
    cudaGetSymbolAddress((void**)&w1e,   g_w1e);
    cudaGetSymbolAddress((void**)&h1e,   g_h1e);
    cudaGetSymbolAddress((void**)&w2e,   g_w2e);
    cudaGetSymbolAddress((void**)&xl1,   g_xl1);
    cudaGetSymbolAddress((void**)&h2,    g_h2);
    cudaGetSymbolAddress((void**)&asrc1, g_asrc1);
    cudaGetSymbolAddress((void**)&adst1, g_adst1);
    cudaGetSymbolAddress((void**)&asrc2, g_asrc2);
    cudaGetSymbolAddress((void**)&adst2, g_adst2);

    static cudaStream_t s_side = nullptr, s_two = nullptr;
    static cudaEvent_t  s_ev0 = nullptr, s_ev1 = nullptr, s_evA = nullptr, s_evSA = nullptr;
    if (!s_side) {
        cudaStreamCreateWithFlags(&s_side, cudaStreamNonBlocking);
        cudaStreamCreateWithFlags(&s_two,  cudaStreamNonBlocking);
        cudaEventCreateWithFlags(&s_ev0,  cudaEventDisableTiming);
        cudaEventCreateWithFlags(&s_ev1,  cudaEventDisableTiming);
        cudaEventCreateWithFlags(&s_evA,  cudaEventDisableTiming);
        cudaEventCreateWithFlags(&s_evSA, cudaEventDisableTiming);
    }

    cudaEventRecord(s_ev0, 0);
    cudaStreamWaitEvent(s_side, s_ev0, 0);

    // side stream: CSR build + cvt_w2
    k_cvt1<<<(NN * IN_DIM + IN_DIM * F1 + 255) / 256, 256>>>(x, W1);        // 0 (main)
    k_csr_init<<<(NN + 255) / 256, 256, 0, s_side>>>();                      // 1
    k_deg<<<(ET + 255) / 256, 256, 0, s_side>>>(ei);                         // 2
    {   // GEMM1 first half: heads 0-3 (columns 0-511); index 3 for ncu
        dim3 g(4, (NN + 127) / 128);
        k_mma_gemm<128, 128, 2, 4, IN_DIM, 3><<<g, 256>>>(                   // 3
            xe, w1e, xl1, NN, F1, K1E, 0, as1, ad1, asrc1, adst1, HEADS);
    }
    cudaEventRecord(s_evA, 0);
    k_scan<<<1, 1024, 0, s_side>>>();                                        // 4
    k_scatter<<<(ET + 255) / 256, 256, 0, s_side>>>(ei);                     // 5
    k_cvt_w2<<<(F1 * ODIM + 255) / 256, 256, 0, s_side>>>(W2);               // 6
    cudaEventRecord(s_ev1, s_side);

    // stream2: smagg1 heads 0-3, overlapped with GEMM1 second half on main
    cudaStreamWaitEvent(s_two, s_evA, 0);
    cudaStreamWaitEvent(s_two, s_ev1, 0);
    k_smagg1<<<NN, 128, 0, s_two>>>(b1, 0);
    cudaEventRecord(s_evSA, s_two);

    {   // GEMM1 second half: heads 4-7 (columns 512-1023)
        dim3 g(4, (NN + 127) / 128);
        k_mma_gemm<128, 128, 2, 4, IN_DIM, 3><<<g, 256>>>(
            xe, w1e, xl1, NN, F1, K1E, 512, as1, ad1, asrc1, adst1, HEADS);
    }
    cudaStreamWaitEvent(0, s_ev1, 0);
    k_smagg1<<<NN, 128>>>(b1, 4);

    cudaStreamWaitEvent(0, s_evSA, 0);
    {   // GEMM2 + fused attn2
        dim3 g(1, (NN + 63) / 64);
        k_mma_gemm<64, 64, 2, 4, F1, 4><<<g, 256>>>(
            h1e, w2e, h2, NN, ODIM, K2E, 0, as2, ad2, asrc2, adst2, 1);
    }
    k_smagg2ln<<<NN, 64>>>(b2, gamma, beta, out);
}